// round 3
// baseline (speedup 1.0000x reference)
#include <cuda_runtime.h>
#include <math.h>
#include <stdint.h>

#define L_    1024
#define NB    4
#define E_    512
#define H_    8
#define D_    32
#define DFF_  2048
#define E2_   256
#define TOK   4096      // L*NB
#define PM    2047      // 2L-1
#define KW    31

// ---------------- scratch (static device globals; no allocation) -------------
__device__ float g_h1[(size_t)TOK * DFF_];
__device__ float g_x[(size_t)TOK * E_];
__device__ float g_qkv[(size_t)TOK * 768];
__device__ float g_p[(size_t)PM * 256 + 256];
__device__ float g_total[(size_t)32 * 1024 * 1024];   // (N,H,L,S)
__device__ float g_ctx[(size_t)TOK * E2_];
__device__ float g_x2[(size_t)TOK * E_];
__device__ float g_y[(size_t)TOK * 1024];
__device__ float g_hglu[(size_t)NB * E_ * L_];
__device__ float g_hct[(size_t)TOK * E_];
__device__ float g_x3[(size_t)TOK * E_];
__device__ float g_x4[(size_t)TOK * E_];

// ------------- double-buffered SGEMM: C = A(MxK) B(NxK)^T + bias (+epi) ------
// EPI: 0 = bias; 1 = bias + DoubleSwish; 2 = bias + residual add
template <int EPI>
__global__ __launch_bounds__(256, 2) void sgemm(
    const float* __restrict__ A, const float* __restrict__ B,
    const float* __restrict__ bias, const float* __restrict__ res,
    float* __restrict__ C, int M, int Nn, int Kk)
{
    __shared__ float As[2][16][128];
    __shared__ float Bs[2][16][128];
    const int tid  = threadIdx.x;
    const int row0 = blockIdx.y * 128;
    const int col0 = blockIdx.x * 128;
    const int trow = (tid / 16) * 8;
    const int tcol = (tid % 16) * 8;
    const int lr = tid / 4;
    const int lc = (tid % 4) * 4;

    float acc[8][8];
#pragma unroll
    for (int i = 0; i < 8; i++)
#pragma unroll
        for (int j = 0; j < 8; j++) acc[i][j] = 0.f;

    float4 a0, a1, b0, b1;
    const float4 z4 = make_float4(0.f, 0.f, 0.f, 0.f);

#define GLOAD(k0) {                                                            \
        int r = row0 + lr;                                                     \
        a0 = (r < M)  ? *(const float4*)(A + (size_t)r * Kk + (k0) + lc) : z4; \
        r = row0 + lr + 64;                                                    \
        a1 = (r < M)  ? *(const float4*)(A + (size_t)r * Kk + (k0) + lc) : z4; \
        r = col0 + lr;                                                         \
        b0 = (r < Nn) ? *(const float4*)(B + (size_t)r * Kk + (k0) + lc) : z4; \
        r = col0 + lr + 64;                                                    \
        b1 = (r < Nn) ? *(const float4*)(B + (size_t)r * Kk + (k0) + lc) : z4; }
#define SSTORE(bf) {                                                           \
        As[bf][lc+0][lr]    = a0.x; As[bf][lc+1][lr]    = a0.y;                \
        As[bf][lc+2][lr]    = a0.z; As[bf][lc+3][lr]    = a0.w;                \
        As[bf][lc+0][lr+64] = a1.x; As[bf][lc+1][lr+64] = a1.y;                \
        As[bf][lc+2][lr+64] = a1.z; As[bf][lc+3][lr+64] = a1.w;                \
        Bs[bf][lc+0][lr]    = b0.x; Bs[bf][lc+1][lr]    = b0.y;                \
        Bs[bf][lc+2][lr]    = b0.z; Bs[bf][lc+3][lr]    = b0.w;                \
        Bs[bf][lc+0][lr+64] = b1.x; Bs[bf][lc+1][lr+64] = b1.y;                \
        Bs[bf][lc+2][lr+64] = b1.z; Bs[bf][lc+3][lr+64] = b1.w; }

    GLOAD(0); SSTORE(0);
    __syncthreads();
    int buf = 0;
    for (int k0 = 0; k0 < Kk; k0 += 16) {
        const bool more = (k0 + 16) < Kk;
        if (more) GLOAD(k0 + 16);
#pragma unroll
        for (int kk = 0; kk < 16; kk++) {
            float4 ra0 = *(const float4*)&As[buf][kk][trow];
            float4 ra1 = *(const float4*)&As[buf][kk][trow + 4];
            float4 rb0 = *(const float4*)&Bs[buf][kk][tcol];
            float4 rb1 = *(const float4*)&Bs[buf][kk][tcol + 4];
            float ra[8] = {ra0.x, ra0.y, ra0.z, ra0.w, ra1.x, ra1.y, ra1.z, ra1.w};
            float rb[8] = {rb0.x, rb0.y, rb0.z, rb0.w, rb1.x, rb1.y, rb1.z, rb1.w};
#pragma unroll
            for (int i = 0; i < 8; i++)
#pragma unroll
                for (int j = 0; j < 8; j++)
                    acc[i][j] = fmaf(ra[i], rb[j], acc[i][j]);
        }
        if (more) SSTORE(buf ^ 1);
        __syncthreads();
        buf ^= 1;
    }
#undef GLOAD
#undef SSTORE

#pragma unroll
    for (int i = 0; i < 8; i++) {
        int row = row0 + trow + i;
        if (row >= M) continue;
#pragma unroll
        for (int j4 = 0; j4 < 2; j4++) {
            int col = col0 + tcol + j4 * 4;
            if (col + 3 >= Nn) {   // scalar tail
                for (int j = 0; j < 4; j++) {
                    int cc = col + j;
                    if (cc >= Nn) break;
                    float v = acc[i][j4 * 4 + j];
                    if (bias) v += bias[cc];
                    if (EPI == 1) v = v / (1.f + expf(1.f - v));
                    if (EPI == 2) v += res[(size_t)row * Nn + cc];
                    C[(size_t)row * Nn + cc] = v;
                }
                continue;
            }
            float4 v = make_float4(acc[i][j4*4+0], acc[i][j4*4+1],
                                   acc[i][j4*4+2], acc[i][j4*4+3]);
            if (bias) {
                float4 bb = *(const float4*)(bias + col);
                v.x += bb.x; v.y += bb.y; v.z += bb.z; v.w += bb.w;
            }
            if (EPI == 1) {
                v.x = v.x / (1.f + expf(1.f - v.x));
                v.y = v.y / (1.f + expf(1.f - v.y));
                v.z = v.z / (1.f + expf(1.f - v.z));
                v.w = v.w / (1.f + expf(1.f - v.w));
            }
            if (EPI == 2) {
                float4 rr = *(const float4*)(res + (size_t)row * Nn + col);
                v.x += rr.x; v.y += rr.y; v.z += rr.z; v.w += rr.w;
            }
            *(float4*)(C + (size_t)row * Nn + col) = v;
        }
    }
}

// ------------- 64x64-tile SGEMM (small shapes, e.g. pos projection) ----------
__global__ __launch_bounds__(256) void sgemm64(
    const float* __restrict__ A, const float* __restrict__ B,
    float* __restrict__ C, int M, int Nn, int Kk)
{
    __shared__ float As[16][68];
    __shared__ float Bs[16][68];
    const int tid  = threadIdx.x;
    const int row0 = blockIdx.y * 64;
    const int col0 = blockIdx.x * 64;
    const int trow = (tid / 16) * 4;
    const int tcol = (tid % 16) * 4;
    const int lr = tid / 4;
    const int lc = (tid % 4) * 4;

    float acc[4][4] = {};
    const float4 z4 = make_float4(0.f, 0.f, 0.f, 0.f);
    for (int k0 = 0; k0 < Kk; k0 += 16) {
        int r = row0 + lr;
        float4 v = (r < M) ? *(const float4*)(A + (size_t)r * Kk + k0 + lc) : z4;
        As[lc+0][lr] = v.x; As[lc+1][lr] = v.y; As[lc+2][lr] = v.z; As[lc+3][lr] = v.w;
        r = col0 + lr;
        float4 w = (r < Nn) ? *(const float4*)(B + (size_t)r * Kk + k0 + lc) : z4;
        Bs[lc+0][lr] = w.x; Bs[lc+1][lr] = w.y; Bs[lc+2][lr] = w.z; Bs[lc+3][lr] = w.w;
        __syncthreads();
#pragma unroll
        for (int kk = 0; kk < 16; kk++) {
            float4 ra = *(const float4*)&As[kk][trow];
            float4 rb = *(const float4*)&Bs[kk][tcol];
            float a[4] = {ra.x, ra.y, ra.z, ra.w};
            float b[4] = {rb.x, rb.y, rb.z, rb.w};
#pragma unroll
            for (int i = 0; i < 4; i++)
#pragma unroll
                for (int j = 0; j < 4; j++)
                    acc[i][j] = fmaf(a[i], b[j], acc[i][j]);
        }
        __syncthreads();
    }
#pragma unroll
    for (int i = 0; i < 4; i++) {
        int row = row0 + trow + i;
        if (row >= M) continue;
#pragma unroll
        for (int j = 0; j < 4; j++) {
            int col = col0 + tcol + j;
            if (col < Nn) C[(size_t)row * Nn + col] = acc[i][j];
        }
    }
}

// -------- fused: total = (ac + rel_shift(bd))*scal + proj_in(asi) -------------
__global__ __launch_bounds__(256) void scores_kernel(
    const float* __restrict__ qkv, const float* __restrict__ p,
    const float* __restrict__ pu, const float* __restrict__ pv,
    const float* __restrict__ asi, const float* __restrict__ projIn,
    float* __restrict__ total)
{
    __shared__ float qu[64][33], qv[64][33], ks[64][33], ps[128][33];
    __shared__ float pin[64];
    const int tid = threadIdx.x;
    const int nh = blockIdx.z;
    const int n = nh >> 3, h = nh & 7;
    const int l0 = blockIdx.y * 64;
    const int s0 = blockIdx.x * 64;
    const int mbase = (L_ - 64) - l0 + s0;

    if (tid < 64) pin[tid] = projIn[tid];
#pragma unroll
    for (int t = 0; t < 8; t++) {
        int flat = tid + 256 * t;
        int r = flat >> 5, dd = flat & 31;
        float u = pu[h * 32 + dd], vb = pv[h * 32 + dd];
        float qval = qkv[(size_t)((l0 + r) * NB + n) * 768 + h * 32 + dd];
        qu[r][dd] = qval + u;
        qv[r][dd] = qval + vb;
        ks[r][dd] = qkv[(size_t)((s0 + r) * NB + n) * 768 + 256 + h * 32 + dd];
    }
#pragma unroll
    for (int t = 0; t < 16; t++) {
        int flat = tid + 256 * t;
        int r = flat >> 5, dd = flat & 31;
        int m = mbase + r;
        ps[r][dd] = (m < PM) ? p[(size_t)m * 256 + h * 32 + dd] : 0.f;
    }
    __syncthreads();

    const int trow = (tid >> 4) * 4;
    const int tcol = (tid & 15) * 4;
    const int pbase = 63 - trow + tcol;
    float ac[4][4] = {}, bd[4][4] = {};
#pragma unroll
    for (int dd = 0; dd < 32; dd++) {
        float ru[4], rv[4], rk[4], rp[7];
#pragma unroll
        for (int i = 0; i < 4; i++) { ru[i] = qu[trow + i][dd]; rv[i] = qv[trow + i][dd]; }
#pragma unroll
        for (int j = 0; j < 4; j++) rk[j] = ks[tcol + j][dd];
#pragma unroll
        for (int t = 0; t < 7; t++) rp[t] = ps[pbase + t - 3][dd];
#pragma unroll
        for (int i = 0; i < 4; i++)
#pragma unroll
            for (int j = 0; j < 4; j++) {
                ac[i][j] = fmaf(ru[i], rk[j], ac[i][j]);
                bd[i][j] = fmaf(rv[i], rp[j - i + 3], bd[i][j]);
            }
    }
    float pg[8];
#pragma unroll
    for (int hh = 0; hh < 8; hh++) pg[hh] = pin[hh * 8 + h];

    const float scal = 0.17677669529663687f;   // 1/sqrt(32)
    size_t base = (((size_t)nh) << 20) + (size_t)(l0 + trow) * L_ + s0 + tcol;
#pragma unroll
    for (int i = 0; i < 4; i++) {
        size_t rowb = base + (size_t)i * L_;
        size_t abase = ((size_t)n << 23) + ((size_t)(l0 + trow + i) << 13)
                     + ((size_t)(s0 + tcol) << 3);
#pragma unroll
        for (int j = 0; j < 4; j++) {
            float4 u0 = *(const float4*)(asi + abase + j * 8);
            float4 u1 = *(const float4*)(asi + abase + j * 8 + 4);
            float sin = u0.x*pg[0] + u0.y*pg[1] + u0.z*pg[2] + u0.w*pg[3]
                      + u1.x*pg[4] + u1.y*pg[5] + u1.z*pg[6] + u1.w*pg[7];
            total[rowb + j] = (ac[i][j] + bd[i][j]) * scal + sin;
        }
    }
}

// ---- fused scores_out + softmax: one block per (n,l) row -----------------------
__global__ __launch_bounds__(256) void out_softmax_kernel(
    float* __restrict__ total, const float* __restrict__ asi,
    const float* __restrict__ projOut, float* __restrict__ scores_out)
{
    __shared__ float ts[8][1028];
    __shared__ float pout[64];
    __shared__ float red[8][8];
    const int tid = threadIdx.x;
    const int b = blockIdx.x;
    const int n = b >> 10, l = b & 1023;
    if (tid < 64) pout[tid] = projOut[tid];

#pragma unroll
    for (int h = 0; h < 8; h++) {
        float4 v = *(const float4*)(total + (((size_t)(n * 8 + h)) << 20)
                                          + ((size_t)l << 10) + tid * 4);
        *(float4*)&ts[h][tid * 4] = v;
    }
    __syncthreads();

    // scores_out[n,l,s,g] = asi[n,l,s,g] + sum_h ts[h][s]*projOut[h,g]
    const int s = tid * 4;
    const size_t abase = ((size_t)n << 23) + ((size_t)l << 13) + ((size_t)s << 3);
#pragma unroll
    for (int js = 0; js < 4; js++) {
        float t8[8];
#pragma unroll
        for (int h = 0; h < 8; h++) t8[h] = ts[h][s + js];
        float4 a0 = *(const float4*)(asi + abase + js * 8);
        float4 a1 = *(const float4*)(asi + abase + js * 8 + 4);
        float o[8] = {a0.x, a0.y, a0.z, a0.w, a1.x, a1.y, a1.z, a1.w};
#pragma unroll
        for (int g = 0; g < 8; g++) {
            float sum = o[g];
#pragma unroll
            for (int h = 0; h < 8; h++) sum = fmaf(t8[h], pout[h * 8 + g], sum);
            o[g] = sum;
        }
        *(float4*)(scores_out + abase + js * 8)     = make_float4(o[0], o[1], o[2], o[3]);
        *(float4*)(scores_out + abase + js * 8 + 4) = make_float4(o[4], o[5], o[6], o[7]);
    }

    // per-head softmax over s (row of 1024)
    float pm[8];
#pragma unroll
    for (int h = 0; h < 8; h++) {
        float m = fmaxf(fmaxf(ts[h][s], ts[h][s+1]), fmaxf(ts[h][s+2], ts[h][s+3]));
#pragma unroll
        for (int o = 16; o > 0; o >>= 1) m = fmaxf(m, __shfl_xor_sync(0xffffffffu, m, o));
        pm[h] = m;
    }
    if ((tid & 31) == 0)
#pragma unroll
        for (int h = 0; h < 8; h++) red[h][tid >> 5] = pm[h];
    __syncthreads();
    float mh[8];
#pragma unroll
    for (int h = 0; h < 8; h++) {
        float m = red[h][0];
#pragma unroll
        for (int w = 1; w < 8; w++) m = fmaxf(m, red[h][w]);
        mh[h] = m;
    }
    __syncthreads();

    float ev[8][4];
    float psum[8];
#pragma unroll
    for (int h = 0; h < 8; h++) {
        float s0 = 0.f;
#pragma unroll
        for (int js = 0; js < 4; js++) {
            float e = expf(ts[h][s + js] - mh[h]);
            ev[h][js] = e;
            s0 += e;
        }
#pragma unroll
        for (int o = 16; o > 0; o >>= 1) s0 += __shfl_xor_sync(0xffffffffu, s0, o);
        psum[h] = s0;
    }
    if ((tid & 31) == 0)
#pragma unroll
        for (int h = 0; h < 8; h++) red[h][tid >> 5] = psum[h];
    __syncthreads();
#pragma unroll
    for (int h = 0; h < 8; h++) {
        float ss = red[h][0] + red[h][1] + red[h][2] + red[h][3]
                 + red[h][4] + red[h][5] + red[h][6] + red[h][7];
        float inv = 1.f / ss;
        float4 o = make_float4(ev[h][0]*inv, ev[h][1]*inv, ev[h][2]*inv, ev[h][3]*inv);
        *(float4*)(total + (((size_t)(n * 8 + h)) << 20) + ((size_t)l << 10) + s) = o;
    }
}

// -------- ctx[l,n,h*32+d] = sum_s attn[n,h,l,s] * v[s,n,h,d] -------------------
__global__ __launch_bounds__(256) void av_kernel(
    const float* __restrict__ attn, const float* __restrict__ qkv,
    float* __restrict__ ctx)
{
    const int nh = blockIdx.y;
    const int n = nh >> 3, h = nh & 7;
    const int l0 = blockIdx.x * 64;
    __shared__ float As[64][65];
    __shared__ float Vs[64][33];
    const int tid = threadIdx.x;
    const int col = tid & 31;
    const int rg  = tid >> 5;
    float acc[8] = {};
    const float* Abase = attn + (((size_t)nh) << 20) + (((size_t)l0) << 10);
    for (int s0 = 0; s0 < 1024; s0 += 64) {
#pragma unroll
        for (int t = 0; t < 4; t++) {
            int f4 = tid + 256 * t;
            int r = f4 >> 4;
            int c4 = (f4 & 15) * 4;
            float4 v = *(const float4*)(Abase + (((size_t)r) << 10) + s0 + c4);
            As[r][c4] = v.x; As[r][c4 + 1] = v.y; As[r][c4 + 2] = v.z; As[r][c4 + 3] = v.w;
        }
#pragma unroll
        for (int t = 0; t < 8; t++) {
            int flat = tid + 256 * t;
            int r = flat >> 5, dd = flat & 31;
            Vs[r][dd] = qkv[(size_t)((s0 + r) * NB + n) * 768 + 512 + h * 32 + dd];
        }
        __syncthreads();
#pragma unroll
        for (int kk = 0; kk < 64; kk++) {
            float vv = Vs[kk][col];
#pragma unroll
            for (int i = 0; i < 8; i++)
                acc[i] = fmaf(As[rg * 8 + i][kk], vv, acc[i]);
        }
        __syncthreads();
    }
#pragma unroll
    for (int i = 0; i < 8; i++) {
        int l = l0 + rg * 8 + i;
        ctx[(size_t)(l * NB + n) * 256 + h * 32 + col] = acc[i];
    }
}

// -------- GLU + transpose to (n,c,l) ------------------------------------------
__global__ __launch_bounds__(256) void glu_kernel(
    const float* __restrict__ y, float* __restrict__ hglu)
{
    size_t idx = (size_t)blockIdx.x * 256 + threadIdx.x;
    int l = (int)(idx & 1023);
    int c = (int)((idx >> 10) & 511);
    int n = (int)(idx >> 19);
    size_t t = (size_t)l * NB + n;
    float a = y[t * 1024 + c];
    float b = y[t * 1024 + c + 512];
    hglu[idx] = a / (1.f + expf(-b));
}

// -------- depthwise conv(K=31) + bias + DoubleSwish ---------------------------
__global__ __launch_bounds__(256) void dwconv_kernel(
    const float* __restrict__ hglu, const float* __restrict__ w,
    const float* __restrict__ b, float* __restrict__ out)
{
    const int nc = blockIdx.x;
    const int c = nc & 511, n = nc >> 9;
    __shared__ float sm[L_ + 30];
    __shared__ float wc[KW];
    const float* row = hglu + (((size_t)nc) << 10);
    for (int i = threadIdx.x; i < L_ + 30; i += 256) {
        int l = i - 15;
        sm[i] = (l >= 0 && l < L_) ? row[l] : 0.f;
    }
    if (threadIdx.x < KW) wc[threadIdx.x] = w[c * KW + threadIdx.x];
    __syncthreads();
    const float bb = b[c];
    for (int l = threadIdx.x; l < L_; l += 256) {
        float s = bb;
#pragma unroll
        for (int k = 0; k < KW; k++) s = fmaf(sm[l + k], wc[k], s);
        out[(size_t)(l * NB + n) * E_ + c] = s / (1.f + expf(1.f - s));
    }
}

// -------- BasicNorm -> d_out ---------------------------------------------------
__global__ __launch_bounds__(128) void norm_kernel(
    const float* __restrict__ x, const float* __restrict__ leps,
    float* __restrict__ out)
{
    __shared__ float red[4];
    const size_t base = (size_t)blockIdx.x * 512;
    float4 v = ((const float4*)(x + base))[threadIdx.x];
    float ss = v.x * v.x + v.y * v.y + v.z * v.z + v.w * v.w;
#pragma unroll
    for (int o = 16; o > 0; o >>= 1) ss += __shfl_xor_sync(0xffffffffu, ss, o);
    if ((threadIdx.x & 31) == 0) red[threadIdx.x >> 5] = ss;
    __syncthreads();
    float tot = red[0] + red[1] + red[2] + red[3];
    float scale = rsqrtf(tot * (1.f / 512.f) + expf(leps[0]));
    ((float4*)(out + base))[threadIdx.x] =
        make_float4(v.x * scale, v.y * scale, v.z * scale, v.w * scale);
}

// ------------------------------- launcher -------------------------------------
extern "C" void kernel_launch(void* const* d_in, const int* in_sizes, int n_in,
                              void* d_out, int out_size)
{
    const float* src      = (const float*)d_in[0];
    const float* pos_emb  = (const float*)d_in[1];
    const float* asi      = (const float*)d_in[2];
    const float* w_in     = (const float*)d_in[3];
    const float* b_in     = (const float*)d_in[4];
    const float* w_pos    = (const float*)d_in[5];
    const float* pbu      = (const float*)d_in[6];
    const float* pbv      = (const float*)d_in[7];
    const float* projIn   = (const float*)d_in[8];
    const float* projOut  = (const float*)d_in[9];
    const float* w_out    = (const float*)d_in[10];
    const float* b_out    = (const float*)d_in[11];
    const float* w_ff1m   = (const float*)d_in[12];
    const float* b_ff1m   = (const float*)d_in[13];
    const float* w_ff2m   = (const float*)d_in[14];
    const float* b_ff2m   = (const float*)d_in[15];
    const float* w_ff1    = (const float*)d_in[16];
    const float* b_ff1    = (const float*)d_in[17];
    const float* w_ff2    = (const float*)d_in[18];
    const float* b_ff2    = (const float*)d_in[19];
    const float* w_pw1    = (const float*)d_in[20];
    const float* b_pw1    = (const float*)d_in[21];
    const float* w_dw     = (const float*)d_in[22];
    const float* b_dw     = (const float*)d_in[23];
    const float* w_pw2    = (const float*)d_in[24];
    const float* b_pw2    = (const float*)d_in[25];
    const float* leps     = (const float*)d_in[26];

    float* out        = (float*)d_out;
    float* out_scores = out + (size_t)TOK * E_;

    float *h1, *x, *qkv, *p, *total, *ctx, *x2, *y, *hglu, *hct, *x3, *x4;
    cudaGetSymbolAddress((void**)&h1,   g_h1);
    cudaGetSymbolAddress((void**)&x,    g_x);
    cudaGetSymbolAddress((void**)&qkv,  g_qkv);
    cudaGetSymbolAddress((void**)&p,    g_p);
    cudaGetSymbolAddress((void**)&total,g_total);
    cudaGetSymbolAddress((void**)&ctx,  g_ctx);
    cudaGetSymbolAddress((void**)&x2,   g_x2);
    cudaGetSymbolAddress((void**)&y,    g_y);
    cudaGetSymbolAddress((void**)&hglu, g_hglu);
    cudaGetSymbolAddress((void**)&hct,  g_hct);
    cudaGetSymbolAddress((void**)&x3,   g_x3);
    cudaGetSymbolAddress((void**)&x4,   g_x4);

    // macaron FFN
    sgemm<1><<<dim3(DFF_ / 128, TOK / 128), 256>>>(src, w_ff1m, b_ff1m, nullptr, h1, TOK, DFF_, E_);
    sgemm<2><<<dim3(E_ / 128, TOK / 128), 256>>>(h1, w_ff2m, b_ff2m, src, x, TOK, E_, DFF_);

    // attention inputs
    sgemm<0><<<dim3(768 / 128, TOK / 128), 256>>>(x, w_in, b_in, nullptr, qkv, TOK, 768, E_);
    sgemm64<<<dim3(4, 32), 256>>>(pos_emb, w_pos, p, PM, 256, E_);

    // scores (fused proj_in) -> scores_out+softmax (fused) -> AV
    scores_kernel<<<dim3(16, 16, 32), 256>>>(qkv, p, pbu, pbv, asi, projIn, total);
    out_softmax_kernel<<<4096, 256>>>(total, asi, projOut, out_scores);
    av_kernel<<<dim3(16, 32), 256>>>(total, qkv, ctx);
    sgemm<2><<<dim3(E_ / 128, TOK / 128), 256>>>(ctx, w_out, b_out, x, x2, TOK, E_, E2_);

    // conv module
    sgemm<0><<<dim3(1024 / 128, TOK / 128), 256>>>(x2, w_pw1, b_pw1, nullptr, y, TOK, 1024, E_);
    glu_kernel<<<8192, 256>>>(y, hglu);
    dwconv_kernel<<<2048, 256>>>(hglu, w_dw, b_dw, hct);
    sgemm<2><<<dim3(E_ / 128, TOK / 128), 256>>>(hct, w_pw2, b_pw2, x2, x3, TOK, E_, E_);

    // final FFN + BasicNorm
    sgemm<1><<<dim3(DFF_ / 128, TOK / 128), 256>>>(x3, w_ff1, b_ff1, nullptr, h1, TOK, DFF_, E_);
    sgemm<2><<<dim3(E_ / 128, TOK / 128), 256>>>(h1, w_ff2, b_ff2, x3, x4, TOK, E_, DFF_);
    norm_kernel<<<TOK, 128>>>(x4, leps, out);
}

// round 4
// speedup vs baseline: 1.0394x; 1.0394x over previous
#include <cuda_runtime.h>
#include <math.h>
#include <stdint.h>

#define L_    1024
#define NB    4
#define E_    512
#define H_    8
#define D_    32
#define DFF_  2048
#define E2_   256
#define TOK   4096      // L*NB
#define PM    2047      // 2L-1
#define KW    31

// ---------------- scratch (static device globals; no allocation) -------------
__device__ float g_h1[(size_t)TOK * DFF_];
__device__ float g_x[(size_t)TOK * E_];
__device__ float g_qkv[(size_t)TOK * 768];
__device__ float g_p[(size_t)PM * 256 + 256];
__device__ float g_total[(size_t)32 * 1024 * 1024];   // (N,H,L,S)
__device__ float g_ctx[(size_t)TOK * E2_];
__device__ float g_x2[(size_t)TOK * E_];
__device__ float g_y[(size_t)TOK * 1024];
__device__ float g_hglu[(size_t)NB * E_ * L_];
__device__ float g_hct[(size_t)TOK * E_];
__device__ float g_x3[(size_t)TOK * E_];
__device__ float g_x4[(size_t)TOK * E_];

// ---------------- SGEMM (R1 single-buffered): C = A(MxK) B(NxK)^T + epi ------
// EPI: 0 = bias; 1 = bias + DoubleSwish; 2 = bias + residual add
template <int EPI>
__global__ __launch_bounds__(256) void sgemm(
    const float* __restrict__ A, const float* __restrict__ B,
    const float* __restrict__ bias, const float* __restrict__ res,
    float* __restrict__ C, int M, int Nn, int Kk)
{
    __shared__ float As[16][128];
    __shared__ float Bs[16][128];
    const int tid  = threadIdx.x;
    const int row0 = blockIdx.y * 128;
    const int col0 = blockIdx.x * 128;
    const int trow = (tid / 16) * 8;
    const int tcol = (tid % 16) * 8;

    float acc[8][8];
#pragma unroll
    for (int i = 0; i < 8; i++)
#pragma unroll
        for (int j = 0; j < 8; j++) acc[i][j] = 0.f;

    const int lr = tid / 4;          // 0..63
    const int lc = (tid % 4) * 4;    // 0,4,8,12

    for (int k0 = 0; k0 < Kk; k0 += 16) {
#pragma unroll
        for (int r = 0; r < 2; r++) {
            int arow = row0 + lr + r * 64;
            float4 v = make_float4(0.f, 0.f, 0.f, 0.f);
            if (arow < M) v = *(const float4*)(A + (size_t)arow * Kk + k0 + lc);
            As[lc + 0][lr + r * 64] = v.x;
            As[lc + 1][lr + r * 64] = v.y;
            As[lc + 2][lr + r * 64] = v.z;
            As[lc + 3][lr + r * 64] = v.w;
            int brow = col0 + lr + r * 64;
            float4 w = make_float4(0.f, 0.f, 0.f, 0.f);
            if (brow < Nn) w = *(const float4*)(B + (size_t)brow * Kk + k0 + lc);
            Bs[lc + 0][lr + r * 64] = w.x;
            Bs[lc + 1][lr + r * 64] = w.y;
            Bs[lc + 2][lr + r * 64] = w.z;
            Bs[lc + 3][lr + r * 64] = w.w;
        }
        __syncthreads();
#pragma unroll
        for (int kk = 0; kk < 16; kk++) {
            float ra[8], rb[8];
#pragma unroll
            for (int i = 0; i < 8; i++) ra[i] = As[kk][trow + i];
#pragma unroll
            for (int j = 0; j < 8; j++) rb[j] = Bs[kk][tcol + j];
#pragma unroll
            for (int i = 0; i < 8; i++)
#pragma unroll
                for (int j = 0; j < 8; j++)
                    acc[i][j] = fmaf(ra[i], rb[j], acc[i][j]);
        }
        __syncthreads();
    }

#pragma unroll
    for (int i = 0; i < 8; i++) {
        int row = row0 + trow + i;
        if (row >= M) continue;
#pragma unroll
        for (int j = 0; j < 8; j++) {
            int col = col0 + tcol + j;
            if (col >= Nn) continue;
            float v = acc[i][j];
            if (bias) v += bias[col];
            if (EPI == 1) v = v / (1.f + expf(1.f - v));     // x*sigmoid(x-1)
            if (EPI == 2) v += res[(size_t)row * Nn + col];
            C[(size_t)row * Nn + col] = v;
        }
    }
}

// ------------- 64x64-tile SGEMM (small shapes, e.g. pos projection) ----------
__global__ __launch_bounds__(256) void sgemm64(
    const float* __restrict__ A, const float* __restrict__ B,
    float* __restrict__ C, int M, int Nn, int Kk)
{
    __shared__ float As[16][68];
    __shared__ float Bs[16][68];
    const int tid  = threadIdx.x;
    const int row0 = blockIdx.y * 64;
    const int col0 = blockIdx.x * 64;
    const int trow = (tid / 16) * 4;
    const int tcol = (tid % 16) * 4;
    const int lr = tid / 4;
    const int lc = (tid % 4) * 4;

    float acc[4][4] = {};
    const float4 z4 = make_float4(0.f, 0.f, 0.f, 0.f);
    for (int k0 = 0; k0 < Kk; k0 += 16) {
        int r = row0 + lr;
        float4 v = (r < M) ? *(const float4*)(A + (size_t)r * Kk + k0 + lc) : z4;
        As[lc+0][lr] = v.x; As[lc+1][lr] = v.y; As[lc+2][lr] = v.z; As[lc+3][lr] = v.w;
        r = col0 + lr;
        float4 w = (r < Nn) ? *(const float4*)(B + (size_t)r * Kk + k0 + lc) : z4;
        Bs[lc+0][lr] = w.x; Bs[lc+1][lr] = w.y; Bs[lc+2][lr] = w.z; Bs[lc+3][lr] = w.w;
        __syncthreads();
#pragma unroll
        for (int kk = 0; kk < 16; kk++) {
            float4 ra = *(const float4*)&As[kk][trow];
            float4 rb = *(const float4*)&Bs[kk][tcol];
            float a[4] = {ra.x, ra.y, ra.z, ra.w};
            float b[4] = {rb.x, rb.y, rb.z, rb.w};
#pragma unroll
            for (int i = 0; i < 4; i++)
#pragma unroll
                for (int j = 0; j < 4; j++)
                    acc[i][j] = fmaf(a[i], b[j], acc[i][j]);
        }
        __syncthreads();
    }
#pragma unroll
    for (int i = 0; i < 4; i++) {
        int row = row0 + trow + i;
        if (row >= M) continue;
#pragma unroll
        for (int j = 0; j < 4; j++) {
            int col = col0 + tcol + j;
            if (col < Nn) C[(size_t)row * Nn + col] = acc[i][j];
        }
    }
}

// -------- total = (ac + rel_shift(bd)) * scal   (write-once, raw scores) -----
__global__ __launch_bounds__(256) void scores_kernel(
    const float* __restrict__ qkv, const float* __restrict__ p,
    const float* __restrict__ pu, const float* __restrict__ pv,
    float* __restrict__ total)
{
    __shared__ float qu[64][33], qv[64][33], ks[64][33], ps[128][33];
    const int tid = threadIdx.x;
    const int nh = blockIdx.z;
    const int n = nh >> 3, h = nh & 7;
    const int l0 = blockIdx.y * 64;
    const int s0 = blockIdx.x * 64;
    const int mbase = (L_ - 64) - l0 + s0;

#pragma unroll
    for (int t = 0; t < 8; t++) {
        int flat = tid + 256 * t;
        int r = flat >> 5, dd = flat & 31;
        float u = pu[h * 32 + dd], vb = pv[h * 32 + dd];
        float qval = qkv[(size_t)((l0 + r) * NB + n) * 768 + h * 32 + dd];
        qu[r][dd] = qval + u;
        qv[r][dd] = qval + vb;
        ks[r][dd] = qkv[(size_t)((s0 + r) * NB + n) * 768 + 256 + h * 32 + dd];
    }
#pragma unroll
    for (int t = 0; t < 16; t++) {
        int flat = tid + 256 * t;
        int r = flat >> 5, dd = flat & 31;
        int m = mbase + r;
        ps[r][dd] = (m < PM) ? p[(size_t)m * 256 + h * 32 + dd] : 0.f;
    }
    __syncthreads();

    const int trow = (tid >> 4) * 4;
    const int tcol = (tid & 15) * 4;
    const int pbase = 63 - trow + tcol;
    float ac[4][4] = {}, bd[4][4] = {};
#pragma unroll
    for (int dd = 0; dd < 32; dd++) {
        float ru[4], rv[4], rk[4], rp[7];
#pragma unroll
        for (int i = 0; i < 4; i++) { ru[i] = qu[trow + i][dd]; rv[i] = qv[trow + i][dd]; }
#pragma unroll
        for (int j = 0; j < 4; j++) rk[j] = ks[tcol + j][dd];
#pragma unroll
        for (int t = 0; t < 7; t++) rp[t] = ps[pbase + t - 3][dd];
#pragma unroll
        for (int i = 0; i < 4; i++)
#pragma unroll
            for (int j = 0; j < 4; j++) {
                ac[i][j] = fmaf(ru[i], rk[j], ac[i][j]);
                bd[i][j] = fmaf(rv[i], rp[j - i + 3], bd[i][j]);
            }
    }
    const float scal = 0.17677669529663687f;   // 1/sqrt(32)
    size_t base = (((size_t)nh) << 20) + (size_t)(l0 + trow) * L_ + s0 + tcol;
#pragma unroll
    for (int i = 0; i < 4; i++) {
        size_t rowb = base + (size_t)i * L_;
#pragma unroll
        for (int j = 0; j < 4; j++)
            total[rowb + j] = (ac[i][j] + bd[i][j]) * scal;
    }
}

// ---- fused proj_in + scores_out + softmax: one block per (n,l) row ------------
// total' = total_raw + proj_in(asi); scores_out = proj_out(total') + asi;
// attn = softmax(total') written in place of total.
__global__ __launch_bounds__(256) void out_softmax_kernel(
    float* __restrict__ total, const float* __restrict__ asi,
    const float* __restrict__ projIn, const float* __restrict__ projOut,
    float* __restrict__ scores_out)
{
    __shared__ float ts[8][1028];
    __shared__ float pin[64], pout[64];
    __shared__ float red[8][8];
    const int tid = threadIdx.x;
    const int b = blockIdx.x;
    const int n = b >> 10, l = b & 1023;
    if (tid < 64) { pin[tid] = projIn[tid]; pout[tid] = projOut[tid]; }

#pragma unroll
    for (int h = 0; h < 8; h++) {
        float4 v = *(const float4*)(total + (((size_t)(n * 8 + h)) << 20)
                                          + ((size_t)l << 10) + tid * 4);
        *(float4*)&ts[h][tid * 4] = v;
    }
    __syncthreads();   // pin/pout visibility

    const int s = tid * 4;
    const size_t abase = ((size_t)n << 23) + ((size_t)l << 13) + ((size_t)s << 3);
    float tn[4][8];    // total' for this thread's 4 s positions, 8 heads
#pragma unroll
    for (int js = 0; js < 4; js++) {
        float4 a0 = *(const float4*)(asi + abase + js * 8);
        float4 a1 = *(const float4*)(asi + abase + js * 8 + 4);
        float a[8] = {a0.x, a0.y, a0.z, a0.w, a1.x, a1.y, a1.z, a1.w};
        // total' = raw + proj_in(asi)
#pragma unroll
        for (int h = 0; h < 8; h++) {
            float t = ts[h][s + js];
#pragma unroll
            for (int g = 0; g < 8; g++) t = fmaf(a[g], pin[g * 8 + h], t);
            tn[js][h] = t;
        }
        // scores_out = asi + proj_out(total')
        float o[8];
#pragma unroll
        for (int g = 0; g < 8; g++) {
            float sum = a[g];
#pragma unroll
            for (int h = 0; h < 8; h++) sum = fmaf(tn[js][h], pout[h * 8 + g], sum);
            o[g] = sum;
        }
        *(float4*)(scores_out + abase + js * 8)     = make_float4(o[0], o[1], o[2], o[3]);
        *(float4*)(scores_out + abase + js * 8 + 4) = make_float4(o[4], o[5], o[6], o[7]);
    }

    // per-head softmax over s (row of 1024), on total'
    float pm[8];
#pragma unroll
    for (int h = 0; h < 8; h++) {
        float m = fmaxf(fmaxf(tn[0][h], tn[1][h]), fmaxf(tn[2][h], tn[3][h]));
#pragma unroll
        for (int o = 16; o > 0; o >>= 1) m = fmaxf(m, __shfl_xor_sync(0xffffffffu, m, o));
        pm[h] = m;
    }
    if ((tid & 31) == 0)
#pragma unroll
        for (int h = 0; h < 8; h++) red[h][tid >> 5] = pm[h];
    __syncthreads();
    float mh[8];
#pragma unroll
    for (int h = 0; h < 8; h++) {
        float m = red[h][0];
#pragma unroll
        for (int w = 1; w < 8; w++) m = fmaxf(m, red[h][w]);
        mh[h] = m;
    }
    __syncthreads();

    float ev[8][4];
    float psum[8];
#pragma unroll
    for (int h = 0; h < 8; h++) {
        float s0 = 0.f;
#pragma unroll
        for (int js = 0; js < 4; js++) {
            float e = expf(tn[js][h] - mh[h]);
            ev[h][js] = e;
            s0 += e;
        }
#pragma unroll
        for (int o = 16; o > 0; o >>= 1) s0 += __shfl_xor_sync(0xffffffffu, s0, o);
        psum[h] = s0;
    }
    if ((tid & 31) == 0)
#pragma unroll
        for (int h = 0; h < 8; h++) red[h][tid >> 5] = psum[h];
    __syncthreads();
#pragma unroll
    for (int h = 0; h < 8; h++) {
        float ss = red[h][0] + red[h][1] + red[h][2] + red[h][3]
                 + red[h][4] + red[h][5] + red[h][6] + red[h][7];
        float inv = 1.f / ss;
        float4 o = make_float4(ev[h][0]*inv, ev[h][1]*inv, ev[h][2]*inv, ev[h][3]*inv);
        *(float4*)(total + (((size_t)(n * 8 + h)) << 20) + ((size_t)l << 10) + s) = o;
    }
}

// -------- ctx[l,n,h*32+d] = sum_s attn[n,h,l,s] * v[s,n,h,d] -------------------
__global__ __launch_bounds__(256) void av_kernel(
    const float* __restrict__ attn, const float* __restrict__ qkv,
    float* __restrict__ ctx)
{
    const int nh = blockIdx.y;
    const int n = nh >> 3, h = nh & 7;
    const int l0 = blockIdx.x * 64;
    __shared__ float As[64][65];
    __shared__ float Vs[64][33];
    const int tid = threadIdx.x;
    const int col = tid & 31;
    const int rg  = tid >> 5;
    float acc[8] = {};
    const float* Abase = attn + (((size_t)nh) << 20) + (((size_t)l0) << 10);
    for (int s0 = 0; s0 < 1024; s0 += 64) {
#pragma unroll
        for (int t = 0; t < 4; t++) {
            int f4 = tid + 256 * t;
            int r = f4 >> 4;
            int c4 = (f4 & 15) * 4;
            float4 v = *(const float4*)(Abase + (((size_t)r) << 10) + s0 + c4);
            As[r][c4] = v.x; As[r][c4 + 1] = v.y; As[r][c4 + 2] = v.z; As[r][c4 + 3] = v.w;
        }
#pragma unroll
        for (int t = 0; t < 8; t++) {
            int flat = tid + 256 * t;
            int r = flat >> 5, dd = flat & 31;
            Vs[r][dd] = qkv[(size_t)((s0 + r) * NB + n) * 768 + 512 + h * 32 + dd];
        }
        __syncthreads();
#pragma unroll
        for (int kk = 0; kk < 64; kk++) {
            float vv = Vs[kk][col];
#pragma unroll
            for (int i = 0; i < 8; i++)
                acc[i] = fmaf(As[rg * 8 + i][kk], vv, acc[i]);
        }
        __syncthreads();
    }
#pragma unroll
    for (int i = 0; i < 8; i++) {
        int l = l0 + rg * 8 + i;
        ctx[(size_t)(l * NB + n) * 256 + h * 32 + col] = acc[i];
    }
}

// -------- GLU + transpose to (n,c,l) ------------------------------------------
__global__ __launch_bounds__(256) void glu_kernel(
    const float* __restrict__ y, float* __restrict__ hglu)
{
    size_t idx = (size_t)blockIdx.x * 256 + threadIdx.x;
    int l = (int)(idx & 1023);
    int c = (int)((idx >> 10) & 511);
    int n = (int)(idx >> 19);
    size_t t = (size_t)l * NB + n;
    float a = y[t * 1024 + c];
    float b = y[t * 1024 + c + 512];
    hglu[idx] = a / (1.f + expf(-b));
}

// -------- depthwise conv(K=31) + bias + DoubleSwish ---------------------------
__global__ __launch_bounds__(256) void dwconv_kernel(
    const float* __restrict__ hglu, const float* __restrict__ w,
    const float* __restrict__ b, float* __restrict__ out)
{
    const int nc = blockIdx.x;
    const int c = nc & 511, n = nc >> 9;
    __shared__ float sm[L_ + 30];
    __shared__ float wc[KW];
    const float* row = hglu + (((size_t)nc) << 10);
    for (int i = threadIdx.x; i < L_ + 30; i += 256) {
        int l = i - 15;
        sm[i] = (l >= 0 && l < L_) ? row[l] : 0.f;
    }
    if (threadIdx.x < KW) wc[threadIdx.x] = w[c * KW + threadIdx.x];
    __syncthreads();
    const float bb = b[c];
    for (int l = threadIdx.x; l < L_; l += 256) {
        float s = bb;
#pragma unroll
        for (int k = 0; k < KW; k++) s = fmaf(sm[l + k], wc[k], s);
        out[(size_t)(l * NB + n) * E_ + c] = s / (1.f + expf(1.f - s));
    }
}

// -------- BasicNorm -> d_out ---------------------------------------------------
__global__ __launch_bounds__(128) void norm_kernel(
    const float* __restrict__ x, const float* __restrict__ leps,
    float* __restrict__ out)
{
    __shared__ float red[4];
    const size_t base = (size_t)blockIdx.x * 512;
    float4 v = ((const float4*)(x + base))[threadIdx.x];
    float ss = v.x * v.x + v.y * v.y + v.z * v.z + v.w * v.w;
#pragma unroll
    for (int o = 16; o > 0; o >>= 1) ss += __shfl_xor_sync(0xffffffffu, ss, o);
    if ((threadIdx.x & 31) == 0) red[threadIdx.x >> 5] = ss;
    __syncthreads();
    float tot = red[0] + red[1] + red[2] + red[3];
    float scale = rsqrtf(tot * (1.f / 512.f) + expf(leps[0]));
    ((float4*)(out + base))[threadIdx.x] =
        make_float4(v.x * scale, v.y * scale, v.z * scale, v.w * scale);
}

// ------------------------------- launcher -------------------------------------
extern "C" void kernel_launch(void* const* d_in, const int* in_sizes, int n_in,
                              void* d_out, int out_size)
{
    const float* src      = (const float*)d_in[0];
    const float* pos_emb  = (const float*)d_in[1];
    const float* asi      = (const float*)d_in[2];
    const float* w_in     = (const float*)d_in[3];
    const float* b_in     = (const float*)d_in[4];
    const float* w_pos    = (const float*)d_in[5];
    const float* pbu      = (const float*)d_in[6];
    const float* pbv      = (const float*)d_in[7];
    const float* projIn   = (const float*)d_in[8];
    const float* projOut  = (const float*)d_in[9];
    const float* w_out    = (const float*)d_in[10];
    const float* b_out    = (const float*)d_in[11];
    const float* w_ff1m   = (const float*)d_in[12];
    const float* b_ff1m   = (const float*)d_in[13];
    const float* w_ff2m   = (const float*)d_in[14];
    const float* b_ff2m   = (const float*)d_in[15];
    const float* w_ff1    = (const float*)d_in[16];
    const float* b_ff1    = (const float*)d_in[17];
    const float* w_ff2    = (const float*)d_in[18];
    const float* b_ff2    = (const float*)d_in[19];
    const float* w_pw1    = (const float*)d_in[20];
    const float* b_pw1    = (const float*)d_in[21];
    const float* w_dw     = (const float*)d_in[22];
    const float* b_dw     = (const float*)d_in[23];
    const float* w_pw2    = (const float*)d_in[24];
    const float* b_pw2    = (const float*)d_in[25];
    const float* leps     = (const float*)d_in[26];

    float* out        = (float*)d_out;
    float* out_scores = out + (size_t)TOK * E_;

    float *h1, *x, *qkv, *p, *total, *ctx, *x2, *y, *hglu, *hct, *x3, *x4;
    cudaGetSymbolAddress((void**)&h1,   g_h1);
    cudaGetSymbolAddress((void**)&x,    g_x);
    cudaGetSymbolAddress((void**)&qkv,  g_qkv);
    cudaGetSymbolAddress((void**)&p,    g_p);
    cudaGetSymbolAddress((void**)&total,g_total);
    cudaGetSymbolAddress((void**)&ctx,  g_ctx);
    cudaGetSymbolAddress((void**)&x2,   g_x2);
    cudaGetSymbolAddress((void**)&y,    g_y);
    cudaGetSymbolAddress((void**)&hglu, g_hglu);
    cudaGetSymbolAddress((void**)&hct,  g_hct);
    cudaGetSymbolAddress((void**)&x3,   g_x3);
    cudaGetSymbolAddress((void**)&x4,   g_x4);

    // macaron FFN
    sgemm<1><<<dim3(DFF_ / 128, TOK / 128), 256>>>(src, w_ff1m, b_ff1m, nullptr, h1, TOK, DFF_, E_);
    sgemm<2><<<dim3(E_ / 128, TOK / 128), 256>>>(h1, w_ff2m, b_ff2m, src, x, TOK, E_, DFF_);

    // attention inputs
    sgemm<0><<<dim3(768 / 128, TOK / 128), 256>>>(x, w_in, b_in, nullptr, qkv, TOK, 768, E_);
    sgemm64<<<dim3(4, 32), 256>>>(pos_emb, w_pos, p, PM, 256, E_);

    // raw scores -> fused proj_in + scores_out + softmax -> AV
    scores_kernel<<<dim3(16, 16, 32), 256>>>(qkv, p, pbu, pbv, total);
    out_softmax_kernel<<<4096, 256>>>(total, asi, projIn, projOut, out_scores);
    av_kernel<<<dim3(16, 32), 256>>>(total, qkv, ctx);
    sgemm<2><<<dim3(E_ / 128, TOK / 128), 256>>>(ctx, w_out, b_out, x, x2, TOK, E_, E2_);

    // conv module
    sgemm<0><<<dim3(1024 / 128, TOK / 128), 256>>>(x2, w_pw1, b_pw1, nullptr, y, TOK, 1024, E_);
    glu_kernel<<<8192, 256>>>(y, hglu);
    dwconv_kernel<<<2048, 256>>>(hglu, w_dw, b_dw, hct);
    sgemm<2><<<dim3(E_ / 128, TOK / 128), 256>>>(hct, w_pw2, b_pw2, x2, x3, TOK, E_, E_);

    // final FFN + BasicNorm
    sgemm<1><<<dim3(DFF_ / 128, TOK / 128), 256>>>(x3, w_ff1, b_ff1, nullptr, h1, TOK, DFF_, E_);
    sgemm<2><<<dim3(E_ / 128, TOK / 128), 256>>>(h1, w_ff2, b_ff2, x3, x4, TOK, E_, DFF_);
    norm_kernel<<<TOK, 128>>>(x4, leps, out);
}

// round 5
// speedup vs baseline: 1.9083x; 1.8360x over previous
#include <cuda_runtime.h>
#include <math.h>
#include <stdint.h>

#define L_    1024
#define NB    4
#define E_    512
#define H_    8
#define D_    32
#define DFF_  2048
#define E2_   256
#define TOK   4096      // L*NB
#define PM    2047      // 2L-1
#define KW    31

// ---------------- scratch (static device globals; no allocation) -------------
__device__ float g_h1[(size_t)TOK * DFF_];
__device__ float g_x[(size_t)TOK * E_];
__device__ float g_qkv[(size_t)TOK * 768];
__device__ float g_p[(size_t)PM * 256 + 256];
__device__ float g_total[(size_t)32 * 1024 * 1024];   // (N,H,L,S)
__device__ float g_ctx[(size_t)TOK * E2_];
__device__ float g_x2[(size_t)TOK * E_];
__device__ float g_y[(size_t)TOK * 1024];
__device__ float g_hglu[(size_t)NB * E_ * L_];
__device__ float g_hct[(size_t)TOK * E_];
__device__ float g_x3[(size_t)TOK * E_];
__device__ float g_x4[(size_t)TOK * E_];

// ---------------- tf32 helpers -------------------------------------------------
__device__ __forceinline__ uint32_t f2tf(float f) {
    uint32_t u;
    asm("cvt.rna.tf32.f32 %0, %1;" : "=r"(u) : "f"(f));
    return u;
}
__device__ __forceinline__ void mma_tf32(float* c, const uint32_t* a, const uint32_t* b) {
    asm volatile(
        "mma.sync.aligned.m16n8k8.row.col.f32.tf32.tf32.f32 "
        "{%0,%1,%2,%3}, {%4,%5,%6,%7}, {%8,%9}, {%0,%1,%2,%3};"
        : "+f"(c[0]), "+f"(c[1]), "+f"(c[2]), "+f"(c[3])
        : "r"(a[0]), "r"(a[1]), "r"(a[2]), "r"(a[3]), "r"(b[0]), "r"(b[1]));
}

// ------------- tensor-core tf32 GEMM: C = A(MxK) B(NxK)^T + bias (+epi) ------
// Requirements: M % 128 == 0, Nn % 128 == 0, Kk % 32 == 0.
// EPI: 0 = bias; 1 = bias + DoubleSwish; 2 = bias + residual add
template <int EPI>
__global__ __launch_bounds__(256) void tgemm(
    const float* __restrict__ A, const float* __restrict__ B,
    const float* __restrict__ bias, const float* __restrict__ res,
    float* __restrict__ C, int M, int Nn, int Kk)
{
    __shared__ uint32_t As[128][36];
    __shared__ uint32_t Bs[128][36];
    const int tid   = threadIdx.x;
    const int wid   = tid >> 5;
    const int lane  = tid & 31;
    const int grp   = lane >> 2;    // 0..7
    const int tig   = lane & 3;     // 0..3
    const int row0  = blockIdx.y * 128;
    const int col0  = blockIdx.x * 128;
    const int wm    = (wid >> 1) * 32;   // warp m offset (0,32,64,96)
    const int wn    = (wid & 1) * 64;    // warp n offset (0,64)

    float acc[2][8][4];
#pragma unroll
    for (int mt = 0; mt < 2; mt++)
#pragma unroll
        for (int nt = 0; nt < 8; nt++)
#pragma unroll
            for (int q = 0; q < 4; q++) acc[mt][nt][q] = 0.f;

    for (int k0 = 0; k0 < Kk; k0 += 32) {
#pragma unroll
        for (int i = 0; i < 4; i++) {
            int f = tid + 256 * i;       // 0..1023
            int r = f >> 3;              // 0..127
            int c = (f & 7) * 4;         // 0..28
            float4 va = *(const float4*)(A + (size_t)(row0 + r) * Kk + k0 + c);
            As[r][c + 0] = f2tf(va.x); As[r][c + 1] = f2tf(va.y);
            As[r][c + 2] = f2tf(va.z); As[r][c + 3] = f2tf(va.w);
            float4 vb = *(const float4*)(B + (size_t)(col0 + r) * Kk + k0 + c);
            Bs[r][c + 0] = f2tf(vb.x); Bs[r][c + 1] = f2tf(vb.y);
            Bs[r][c + 2] = f2tf(vb.z); Bs[r][c + 3] = f2tf(vb.w);
        }
        __syncthreads();
#pragma unroll
        for (int k8 = 0; k8 < 4; k8++) {
            const int kb = k8 * 8;
            uint32_t a[2][4], b[8][2];
#pragma unroll
            for (int mt = 0; mt < 2; mt++) {
                int mr = wm + mt * 16 + grp;
                a[mt][0] = As[mr][kb + tig];
                a[mt][1] = As[mr + 8][kb + tig];
                a[mt][2] = As[mr][kb + tig + 4];
                a[mt][3] = As[mr + 8][kb + tig + 4];
            }
#pragma unroll
            for (int nt = 0; nt < 8; nt++) {
                int nr = wn + nt * 8 + grp;
                b[nt][0] = Bs[nr][kb + tig];
                b[nt][1] = Bs[nr][kb + tig + 4];
            }
#pragma unroll
            for (int mt = 0; mt < 2; mt++)
#pragma unroll
                for (int nt = 0; nt < 8; nt++)
                    mma_tf32(acc[mt][nt], a[mt], b[nt]);
        }
        __syncthreads();
    }

    // epilogue: c0/c1 -> row grp, cols tig*2, tig*2+1; c2/c3 -> row grp+8
#pragma unroll
    for (int mt = 0; mt < 2; mt++) {
        int rbase = row0 + wm + mt * 16 + grp;
#pragma unroll
        for (int nt = 0; nt < 8; nt++) {
            int col = col0 + wn + nt * 8 + tig * 2;
            float2 bb = *(const float2*)(bias + col);
#pragma unroll
            for (int half = 0; half < 2; half++) {
                int row = rbase + half * 8;
                float v0 = acc[mt][nt][half * 2 + 0] + bb.x;
                float v1 = acc[mt][nt][half * 2 + 1] + bb.y;
                if (EPI == 1) {
                    v0 = v0 / (1.f + expf(1.f - v0));
                    v1 = v1 / (1.f + expf(1.f - v1));
                }
                if (EPI == 2) {
                    float2 rr = *(const float2*)(res + (size_t)row * Nn + col);
                    v0 += rr.x; v1 += rr.y;
                }
                *(float2*)(C + (size_t)row * Nn + col) = make_float2(v0, v1);
            }
        }
    }
}

// ------------- 64x64-tile fp32 SGEMM (pos projection, M=2047) ----------------
__global__ __launch_bounds__(256) void sgemm64(
    const float* __restrict__ A, const float* __restrict__ B,
    float* __restrict__ C, int M, int Nn, int Kk)
{
    __shared__ float As[16][68];
    __shared__ float Bs[16][68];
    const int tid  = threadIdx.x;
    const int row0 = blockIdx.y * 64;
    const int col0 = blockIdx.x * 64;
    const int trow = (tid / 16) * 4;
    const int tcol = (tid % 16) * 4;
    const int lr = tid / 4;
    const int lc = (tid % 4) * 4;

    float acc[4][4] = {};
    const float4 z4 = make_float4(0.f, 0.f, 0.f, 0.f);
    for (int k0 = 0; k0 < Kk; k0 += 16) {
        int r = row0 + lr;
        float4 v = (r < M) ? *(const float4*)(A + (size_t)r * Kk + k0 + lc) : z4;
        As[lc+0][lr] = v.x; As[lc+1][lr] = v.y; As[lc+2][lr] = v.z; As[lc+3][lr] = v.w;
        r = col0 + lr;
        float4 w = (r < Nn) ? *(const float4*)(B + (size_t)r * Kk + k0 + lc) : z4;
        Bs[lc+0][lr] = w.x; Bs[lc+1][lr] = w.y; Bs[lc+2][lr] = w.z; Bs[lc+3][lr] = w.w;
        __syncthreads();
#pragma unroll
        for (int kk = 0; kk < 16; kk++) {
            float4 ra = *(const float4*)&As[kk][trow];
            float4 rb = *(const float4*)&Bs[kk][tcol];
            float a[4] = {ra.x, ra.y, ra.z, ra.w};
            float b[4] = {rb.x, rb.y, rb.z, rb.w};
#pragma unroll
            for (int i = 0; i < 4; i++)
#pragma unroll
                for (int j = 0; j < 4; j++)
                    acc[i][j] = fmaf(a[i], b[j], acc[i][j]);
        }
        __syncthreads();
    }
#pragma unroll
    for (int i = 0; i < 4; i++) {
        int row = row0 + trow + i;
        if (row >= M) continue;
#pragma unroll
        for (int j = 0; j < 4; j++) {
            int col = col0 + tcol + j;
            if (col < Nn) C[(size_t)row * Nn + col] = acc[i][j];
        }
    }
}

// -------- total = (ac + rel_shift(bd)) * scal   (write-once, raw scores) -----
__global__ __launch_bounds__(256) void scores_kernel(
    const float* __restrict__ qkv, const float* __restrict__ p,
    const float* __restrict__ pu, const float* __restrict__ pv,
    float* __restrict__ total)
{
    __shared__ float qu[64][33], qv[64][33], ks[64][33], ps[128][33];
    const int tid = threadIdx.x;
    const int nh = blockIdx.z;
    const int n = nh >> 3, h = nh & 7;
    const int l0 = blockIdx.y * 64;
    const int s0 = blockIdx.x * 64;
    const int mbase = (L_ - 64) - l0 + s0;

#pragma unroll
    for (int t = 0; t < 8; t++) {
        int flat = tid + 256 * t;
        int r = flat >> 5, dd = flat & 31;
        float u = pu[h * 32 + dd], vb = pv[h * 32 + dd];
        float qval = qkv[(size_t)((l0 + r) * NB + n) * 768 + h * 32 + dd];
        qu[r][dd] = qval + u;
        qv[r][dd] = qval + vb;
        ks[r][dd] = qkv[(size_t)((s0 + r) * NB + n) * 768 + 256 + h * 32 + dd];
    }
#pragma unroll
    for (int t = 0; t < 16; t++) {
        int flat = tid + 256 * t;
        int r = flat >> 5, dd = flat & 31;
        int m = mbase + r;
        ps[r][dd] = (m < PM) ? p[(size_t)m * 256 + h * 32 + dd] : 0.f;
    }
    __syncthreads();

    const int trow = (tid >> 4) * 4;
    const int tcol = (tid & 15) * 4;
    const int pbase = 63 - trow + tcol;
    float ac[4][4] = {}, bd[4][4] = {};
#pragma unroll
    for (int dd = 0; dd < 32; dd++) {
        float ru[4], rv[4], rk[4], rp[7];
#pragma unroll
        for (int i = 0; i < 4; i++) { ru[i] = qu[trow + i][dd]; rv[i] = qv[trow + i][dd]; }
#pragma unroll
        for (int j = 0; j < 4; j++) rk[j] = ks[tcol + j][dd];
#pragma unroll
        for (int t = 0; t < 7; t++) rp[t] = ps[pbase + t - 3][dd];
#pragma unroll
        for (int i = 0; i < 4; i++)
#pragma unroll
            for (int j = 0; j < 4; j++) {
                ac[i][j] = fmaf(ru[i], rk[j], ac[i][j]);
                bd[i][j] = fmaf(rv[i], rp[j - i + 3], bd[i][j]);
            }
    }
    const float scal = 0.17677669529663687f;   // 1/sqrt(32)
    size_t base = (((size_t)nh) << 20) + (size_t)(l0 + trow) * L_ + s0 + tcol;
#pragma unroll
    for (int i = 0; i < 4; i++) {
        size_t rowb = base + (size_t)i * L_;
#pragma unroll
        for (int j = 0; j < 4; j++)
            total[rowb + j] = (ac[i][j] + bd[i][j]) * scal;
    }
}

// ---- fused proj_in + scores_out + softmax: one block per (n,l) row ------------
// total' = raw + proj_in(asi); scores_out = proj_out(total') + asi;
// attn = softmax(total') written in place of total. total' staged in smem.
__global__ __launch_bounds__(256) void out_softmax_kernel(
    float* __restrict__ total, const float* __restrict__ asi,
    const float* __restrict__ projIn, const float* __restrict__ projOut,
    float* __restrict__ scores_out)
{
    __shared__ float ts[8][1028];
    __shared__ float pin[64], pout[64];
    __shared__ float red[8][8];
    const int tid = threadIdx.x;
    const int b = blockIdx.x;
    const int n = b >> 10, l = b & 1023;
    if (tid < 64) { pin[tid] = projIn[tid]; pout[tid] = projOut[tid]; }

#pragma unroll
    for (int h = 0; h < 8; h++) {
        float4 v = *(const float4*)(total + (((size_t)(n * 8 + h)) << 20)
                                          + ((size_t)l << 10) + tid * 4);
        *(float4*)&ts[h][tid * 4] = v;
    }
    __syncthreads();

    const int s = tid * 4;
    const size_t abase = ((size_t)n << 23) + ((size_t)l << 13) + ((size_t)s << 3);
    for (int js = 0; js < 4; js++) {
        float4 a0 = *(const float4*)(asi + abase + js * 8);
        float4 a1 = *(const float4*)(asi + abase + js * 8 + 4);
        float a[8] = {a0.x, a0.y, a0.z, a0.w, a1.x, a1.y, a1.z, a1.w};
        float tn8[8];
#pragma unroll
        for (int h = 0; h < 8; h++) {
            float t = ts[h][s + js];
#pragma unroll
            for (int g = 0; g < 8; g++) t = fmaf(a[g], pin[g * 8 + h], t);
            tn8[h] = t;
        }
        float o[8];
#pragma unroll
        for (int g = 0; g < 8; g++) {
            float sum = a[g];
#pragma unroll
            for (int h = 0; h < 8; h++) sum = fmaf(tn8[h], pout[h * 8 + g], sum);
            o[g] = sum;
        }
        *(float4*)(scores_out + abase + js * 8)     = make_float4(o[0], o[1], o[2], o[3]);
        *(float4*)(scores_out + abase + js * 8 + 4) = make_float4(o[4], o[5], o[6], o[7]);
#pragma unroll
        for (int h = 0; h < 8; h++) ts[h][s + js] = tn8[h];   // own cells only
    }

    // per-head softmax over s (1024), totals staged in ts
    float mh[8];
#pragma unroll
    for (int h = 0; h < 8; h++) {
        float m = fmaxf(fmaxf(ts[h][s], ts[h][s+1]), fmaxf(ts[h][s+2], ts[h][s+3]));
#pragma unroll
        for (int o = 16; o > 0; o >>= 1) m = fmaxf(m, __shfl_xor_sync(0xffffffffu, m, o));
        mh[h] = m;
    }
    if ((tid & 31) == 0)
#pragma unroll
        for (int h = 0; h < 8; h++) red[h][tid >> 5] = mh[h];
    __syncthreads();
#pragma unroll
    for (int h = 0; h < 8; h++) {
        float m = red[h][0];
#pragma unroll
        for (int w = 1; w < 8; w++) m = fmaxf(m, red[h][w]);
        mh[h] = m;
    }
    __syncthreads();

    float sh[8];
#pragma unroll
    for (int h = 0; h < 8; h++) {
        float s0 = 0.f;
#pragma unroll
        for (int js = 0; js < 4; js++) {
            float e = expf(ts[h][s + js] - mh[h]);
            ts[h][s + js] = e;
            s0 += e;
        }
#pragma unroll
        for (int o = 16; o > 0; o >>= 1) s0 += __shfl_xor_sync(0xffffffffu, s0, o);
        sh[h] = s0;
    }
    if ((tid & 31) == 0)
#pragma unroll
        for (int h = 0; h < 8; h++) red[h][tid >> 5] = sh[h];
    __syncthreads();
#pragma unroll
    for (int h = 0; h < 8; h++) {
        float ss = red[h][0] + red[h][1] + red[h][2] + red[h][3]
                 + red[h][4] + red[h][5] + red[h][6] + red[h][7];
        float inv = 1.f / ss;
        float4 o = make_float4(ts[h][s]*inv, ts[h][s+1]*inv, ts[h][s+2]*inv, ts[h][s+3]*inv);
        *(float4*)(total + (((size_t)(n * 8 + h)) << 20) + ((size_t)l << 10) + s) = o;
    }
}

// -------- ctx[l,n,h*32+d] = sum_s attn[n,h,l,s] * v[s,n,h,d] -------------------
__global__ __launch_bounds__(256) void av_kernel(
    const float* __restrict__ attn, const float* __restrict__ qkv,
    float* __restrict__ ctx)
{
    const int nh = blockIdx.y;
    const int n = nh >> 3, h = nh & 7;
    const int l0 = blockIdx.x * 64;
    __shared__ float As[64][65];
    __shared__ float Vs[64][33];
    const int tid = threadIdx.x;
    const int col = tid & 31;
    const int rg  = tid >> 5;
    float acc[8] = {};
    const float* Abase = attn + (((size_t)nh) << 20) + (((size_t)l0) << 10);
    for (int s0 = 0; s0 < 1024; s0 += 64) {
#pragma unroll
        for (int t = 0; t < 4; t++) {
            int f4 = tid + 256 * t;
            int r = f4 >> 4;
            int c4 = (f4 & 15) * 4;
            float4 v = *(const float4*)(Abase + (((size_t)r) << 10) + s0 + c4);
            As[r][c4] = v.x; As[r][c4 + 1] = v.y; As[r][c4 + 2] = v.z; As[r][c4 + 3] = v.w;
        }
#pragma unroll
        for (int t = 0; t < 8; t++) {
            int flat = tid + 256 * t;
            int r = flat >> 5, dd = flat & 31;
            Vs[r][dd] = qkv[(size_t)((s0 + r) * NB + n) * 768 + 512 + h * 32 + dd];
        }
        __syncthreads();
#pragma unroll
        for (int kk = 0; kk < 64; kk++) {
            float vv = Vs[kk][col];
#pragma unroll
            for (int i = 0; i < 8; i++)
                acc[i] = fmaf(As[rg * 8 + i][kk], vv, acc[i]);
        }
        __syncthreads();
    }
#pragma unroll
    for (int i = 0; i < 8; i++) {
        int l = l0 + rg * 8 + i;
        ctx[(size_t)(l * NB + n) * 256 + h * 32 + col] = acc[i];
    }
}

// -------- GLU + transpose to (n,c,l) ------------------------------------------
__global__ __launch_bounds__(256) void glu_kernel(
    const float* __restrict__ y, float* __restrict__ hglu)
{
    size_t idx = (size_t)blockIdx.x * 256 + threadIdx.x;
    int l = (int)(idx & 1023);
    int c = (int)((idx >> 10) & 511);
    int n = (int)(idx >> 19);
    size_t t = (size_t)l * NB + n;
    float a = y[t * 1024 + c];
    float b = y[t * 1024 + c + 512];
    hglu[idx] = a / (1.f + expf(-b));
}

// -------- depthwise conv(K=31) + bias + DoubleSwish ---------------------------
__global__ __launch_bounds__(256) void dwconv_kernel(
    const float* __restrict__ hglu, const float* __restrict__ w,
    const float* __restrict__ b, float* __restrict__ out)
{
    const int nc = blockIdx.x;
    const int c = nc & 511, n = nc >> 9;
    __shared__ float sm[L_ + 30];
    __shared__ float wc[KW];
    const float* row = hglu + (((size_t)nc) << 10);
    for (int i = threadIdx.x; i < L_ + 30; i += 256) {
        int l = i - 15;
        sm[i] = (l >= 0 && l < L_) ? row[l] : 0.f;
    }
    if (threadIdx.x < KW) wc[threadIdx.x] = w[c * KW + threadIdx.x];
    __syncthreads();
    const float bb = b[c];
    for (int l = threadIdx.x; l < L_; l += 256) {
        float s = bb;
#pragma unroll
        for (int k = 0; k < KW; k++) s = fmaf(sm[l + k], wc[k], s);
        out[(size_t)(l * NB + n) * E_ + c] = s / (1.f + expf(1.f - s));
    }
}

// -------- BasicNorm -> d_out ---------------------------------------------------
__global__ __launch_bounds__(128) void norm_kernel(
    const float* __restrict__ x, const float* __restrict__ leps,
    float* __restrict__ out)
{
    __shared__ float red[4];
    const size_t base = (size_t)blockIdx.x * 512;
    float4 v = ((const float4*)(x + base))[threadIdx.x];
    float ss = v.x * v.x + v.y * v.y + v.z * v.z + v.w * v.w;
#pragma unroll
    for (int o = 16; o > 0; o >>= 1) ss += __shfl_xor_sync(0xffffffffu, ss, o);
    if ((threadIdx.x & 31) == 0) red[threadIdx.x >> 5] = ss;
    __syncthreads();
    float tot = red[0] + red[1] + red[2] + red[3];
    float scale = rsqrtf(tot * (1.f / 512.f) + expf(leps[0]));
    ((float4*)(out + base))[threadIdx.x] =
        make_float4(v.x * scale, v.y * scale, v.z * scale, v.w * scale);
}

// ------------------------------- launcher -------------------------------------
extern "C" void kernel_launch(void* const* d_in, const int* in_sizes, int n_in,
                              void* d_out, int out_size)
{
    const float* src      = (const float*)d_in[0];
    const float* pos_emb  = (const float*)d_in[1];
    const float* asi      = (const float*)d_in[2];
    const float* w_in     = (const float*)d_in[3];
    const float* b_in     = (const float*)d_in[4];
    const float* w_pos    = (const float*)d_in[5];
    const float* pbu      = (const float*)d_in[6];
    const float* pbv      = (const float*)d_in[7];
    const float* projIn   = (const float*)d_in[8];
    const float* projOut  = (const float*)d_in[9];
    const float* w_out    = (const float*)d_in[10];
    const float* b_out    = (const float*)d_in[11];
    const float* w_ff1m   = (const float*)d_in[12];
    const float* b_ff1m   = (const float*)d_in[13];
    const float* w_ff2m   = (const float*)d_in[14];
    const float* b_ff2m   = (const float*)d_in[15];
    const float* w_ff1    = (const float*)d_in[16];
    const float* b_ff1    = (const float*)d_in[17];
    const float* w_ff2    = (const float*)d_in[18];
    const float* b_ff2    = (const float*)d_in[19];
    const float* w_pw1    = (const float*)d_in[20];
    const float* b_pw1    = (const float*)d_in[21];
    const float* w_dw     = (const float*)d_in[22];
    const float* b_dw     = (const float*)d_in[23];
    const float* w_pw2    = (const float*)d_in[24];
    const float* b_pw2    = (const float*)d_in[25];
    const float* leps     = (const float*)d_in[26];

    float* out        = (float*)d_out;
    float* out_scores = out + (size_t)TOK * E_;

    float *h1, *x, *qkv, *p, *total, *ctx, *x2, *y, *hglu, *hct, *x3, *x4;
    cudaGetSymbolAddress((void**)&h1,   g_h1);
    cudaGetSymbolAddress((void**)&x,    g_x);
    cudaGetSymbolAddress((void**)&qkv,  g_qkv);
    cudaGetSymbolAddress((void**)&p,    g_p);
    cudaGetSymbolAddress((void**)&total,g_total);
    cudaGetSymbolAddress((void**)&ctx,  g_ctx);
    cudaGetSymbolAddress((void**)&x2,   g_x2);
    cudaGetSymbolAddress((void**)&y,    g_y);
    cudaGetSymbolAddress((void**)&hglu, g_hglu);
    cudaGetSymbolAddress((void**)&hct,  g_hct);
    cudaGetSymbolAddress((void**)&x3,   g_x3);
    cudaGetSymbolAddress((void**)&x4,   g_x4);

    // macaron FFN
    tgemm<1><<<dim3(DFF_ / 128, TOK / 128), 256>>>(src, w_ff1m, b_ff1m, nullptr, h1, TOK, DFF_, E_);
    tgemm<2><<<dim3(E_ / 128, TOK / 128), 256>>>(h1, w_ff2m, b_ff2m, src, x, TOK, E_, DFF_);

    // attention inputs
    tgemm<0><<<dim3(768 / 128, TOK / 128), 256>>>(x, w_in, b_in, nullptr, qkv, TOK, 768, E_);
    sgemm64<<<dim3(4, 32), 256>>>(pos_emb, w_pos, p, PM, 256, E_);

    // raw scores -> fused proj_in + scores_out + softmax -> AV
    scores_kernel<<<dim3(16, 16, 32), 256>>>(qkv, p, pbu, pbv, total);
    out_softmax_kernel<<<4096, 256>>>(total, asi, projIn, projOut, out_scores);
    av_kernel<<<dim3(16, 32), 256>>>(total, qkv, ctx);
    tgemm<2><<<dim3(E_ / 128, TOK / 128), 256>>>(ctx, w_out, b_out, x, x2, TOK, E_, E2_);

    // conv module
    tgemm<0><<<dim3(1024 / 128, TOK / 128), 256>>>(x2, w_pw1, b_pw1, nullptr, y, TOK, 1024, E_);
    glu_kernel<<<8192, 256>>>(y, hglu);
    dwconv_kernel<<<2048, 256>>>(hglu, w_dw, b_dw, hct);
    tgemm<2><<<dim3(E_ / 128, TOK / 128), 256>>>(hct, w_pw2, b_pw2, x2, x3, TOK, E_, E_);

    // final FFN + BasicNorm
    tgemm<1><<<dim3(DFF_ / 128, TOK / 128), 256>>>(x3, w_ff1, b_ff1, nullptr, h1, TOK, DFF_, E_);
    tgemm<2><<<dim3(E_ / 128, TOK / 128), 256>>>(h1, w_ff2, b_ff2, x3, x4, TOK, E_, DFF_);
    norm_kernel<<<TOK, 128>>>(x4, leps, out);
}

// round 6
// speedup vs baseline: 2.2288x; 1.1680x over previous
#include <cuda_runtime.h>
#include <math.h>
#include <stdint.h>

#define L_    1024
#define NB    4
#define E_    512
#define H_    8
#define D_    32
#define DFF_  2048
#define E2_   256
#define TOK   4096      // L*NB
#define PM    2047      // 2L-1
#define KW    31

// ---------------- scratch (static device globals; no allocation) -------------
__device__ float g_h1[(size_t)TOK * DFF_];
__device__ float g_x[(size_t)TOK * E_];
__device__ float g_qkv[(size_t)TOK * 768];
__device__ float g_p[(size_t)2048 * 256];
__device__ float g_total[(size_t)32 * 1024 * 1024];   // (N,H,L,S)
__device__ float g_ctx[(size_t)TOK * E2_];
__device__ float g_x2[(size_t)TOK * E_];
__device__ float g_y[(size_t)TOK * 1024];
__device__ float g_hglu[(size_t)NB * E_ * L_];
__device__ float g_hct[(size_t)TOK * E_];
__device__ float g_x3[(size_t)TOK * E_];
__device__ float g_x4[(size_t)TOK * E_];

// ---------------- tf32 / cp.async helpers -------------------------------------
__device__ __forceinline__ uint32_t f2tf(float f) {
    uint32_t u;
    asm("cvt.rna.tf32.f32 %0, %1;" : "=r"(u) : "f"(f));
    return u;
}
__device__ __forceinline__ void mma_tf32(float* c, const uint32_t* a, const uint32_t* b) {
    asm volatile(
        "mma.sync.aligned.m16n8k8.row.col.f32.tf32.tf32.f32 "
        "{%0,%1,%2,%3}, {%4,%5,%6,%7}, {%8,%9}, {%0,%1,%2,%3};"
        : "+f"(c[0]), "+f"(c[1]), "+f"(c[2]), "+f"(c[3])
        : "r"(a[0]), "r"(a[1]), "r"(a[2]), "r"(a[3]), "r"(b[0]), "r"(b[1]));
}
__device__ __forceinline__ void cp16(void* dst_smem, const void* src) {
    uint32_t d = (uint32_t)__cvta_generic_to_shared(dst_smem);
    asm volatile("cp.async.ca.shared.global [%0], [%1], 16;\n" :: "r"(d), "l"(src));
}

// ------------- cp.async double-buffered tf32 GEMM ----------------------------
// C = A(MxK) B(NxK)^T + bias (+epi). Nn % 128 == 0, Kk % 32 == 0.
// A rows are clamped to M-1 on load; stores guarded by row < M (so M need not
// be a multiple of 128).
// EPI: 0 = bias; 1 = bias + DoubleSwish; 2 = bias + residual add
#define TG_STRIDE 36
#define TG_BUFELT (128 * TG_STRIDE)
template <int EPI>
__global__ __launch_bounds__(256) void tgemm(
    const float* __restrict__ A, const float* __restrict__ B,
    const float* __restrict__ bias, const float* __restrict__ res,
    float* __restrict__ C, int M, int Nn, int Kk)
{
    extern __shared__ float smem[];
    float* Af = smem;                    // [2][128][36]
    float* Bf = smem + 2 * TG_BUFELT;    // [2][128][36]

    const int tid   = threadIdx.x;
    const int wid   = tid >> 5;
    const int lane  = tid & 31;
    const int grp   = lane >> 2;    // 0..7
    const int tig   = lane & 3;     // 0..3
    const int row0  = blockIdx.y * 128;
    const int col0  = blockIdx.x * 128;
    const int wm    = (wid >> 1) * 32;   // warp m offset (0,32,64,96)
    const int wn    = (wid & 1) * 64;    // warp n offset (0,64)

    float acc[2][8][4];
#pragma unroll
    for (int mt = 0; mt < 2; mt++)
#pragma unroll
        for (int nt = 0; nt < 8; nt++)
#pragma unroll
            for (int q = 0; q < 4; q++) acc[mt][nt][q] = 0.f;

    const int lrr = tid >> 3;            // 0..31 base row per thread group
    const int lcc = (tid & 7) * 4;       // 0..28

#define LOADTILE(t, bf) {                                                       \
        const int kk0 = (t) * 32;                                               \
        _Pragma("unroll")                                                       \
        for (int i = 0; i < 4; i++) {                                           \
            int r = lrr + 32 * i;                                               \
            int ar = row0 + r; if (ar >= M) ar = M - 1;                         \
            cp16(&Af[(bf) * TG_BUFELT + r * TG_STRIDE + lcc],                   \
                 A + (size_t)ar * Kk + kk0 + lcc);                              \
            cp16(&Bf[(bf) * TG_BUFELT + r * TG_STRIDE + lcc],                   \
                 B + (size_t)(col0 + r) * Kk + kk0 + lcc);                      \
        }                                                                       \
        asm volatile("cp.async.commit_group;\n" ::); }

    const int ntile = Kk >> 5;
    LOADTILE(0, 0);
    int buf = 0;
    for (int t = 0; t < ntile; t++) {
        if (t + 1 < ntile) {
            LOADTILE(t + 1, buf ^ 1);
            asm volatile("cp.async.wait_group 1;\n" ::);
        } else {
            asm volatile("cp.async.wait_group 0;\n" ::);
        }
        __syncthreads();
        const float* Ab = Af + buf * TG_BUFELT;
        const float* Bb = Bf + buf * TG_BUFELT;
#pragma unroll
        for (int k8 = 0; k8 < 4; k8++) {
            const int kb = k8 * 8;
            uint32_t a[2][4], b[8][2];
#pragma unroll
            for (int mt = 0; mt < 2; mt++) {
                int mr = wm + mt * 16 + grp;
                a[mt][0] = f2tf(Ab[mr * TG_STRIDE + kb + tig]);
                a[mt][1] = f2tf(Ab[(mr + 8) * TG_STRIDE + kb + tig]);
                a[mt][2] = f2tf(Ab[mr * TG_STRIDE + kb + tig + 4]);
                a[mt][3] = f2tf(Ab[(mr + 8) * TG_STRIDE + kb + tig + 4]);
            }
#pragma unroll
            for (int nt = 0; nt < 8; nt++) {
                int nr = wn + nt * 8 + grp;
                b[nt][0] = f2tf(Bb[nr * TG_STRIDE + kb + tig]);
                b[nt][1] = f2tf(Bb[nr * TG_STRIDE + kb + tig + 4]);
            }
#pragma unroll
            for (int mt = 0; mt < 2; mt++)
#pragma unroll
                for (int nt = 0; nt < 8; nt++)
                    mma_tf32(acc[mt][nt], a[mt], b[nt]);
        }
        __syncthreads();
        buf ^= 1;
    }
#undef LOADTILE

    // epilogue: c0/c1 -> row grp, cols tig*2..+1; c2/c3 -> row grp+8
#pragma unroll
    for (int mt = 0; mt < 2; mt++) {
        int rbase = row0 + wm + mt * 16 + grp;
#pragma unroll
        for (int nt = 0; nt < 8; nt++) {
            int col = col0 + wn + nt * 8 + tig * 2;
            float2 bb = make_float2(0.f, 0.f);
            if (bias) bb = *(const float2*)(bias + col);
#pragma unroll
            for (int half = 0; half < 2; half++) {
                int row = rbase + half * 8;
                if (row >= M) continue;
                float v0 = acc[mt][nt][half * 2 + 0] + bb.x;
                float v1 = acc[mt][nt][half * 2 + 1] + bb.y;
                if (EPI == 1) {
                    v0 = v0 / (1.f + expf(1.f - v0));
                    v1 = v1 / (1.f + expf(1.f - v1));
                }
                if (EPI == 2) {
                    float2 rr = *(const float2*)(res + (size_t)row * Nn + col);
                    v0 += rr.x; v1 += rr.y;
                }
                *(float2*)(C + (size_t)row * Nn + col) = make_float2(v0, v1);
            }
        }
    }
}
#define TG_SMEM (4 * TG_BUFELT * (int)sizeof(float))   // 73728 bytes

// -------- total = (ac + rel_shift(bd)) * scal   (write-once, raw scores) -----
__global__ __launch_bounds__(256) void scores_kernel(
    const float* __restrict__ qkv, const float* __restrict__ p,
    const float* __restrict__ pu, const float* __restrict__ pv,
    float* __restrict__ total)
{
    __shared__ float qu[64][33], qv[64][33], ks[64][33], ps[128][33];
    const int tid = threadIdx.x;
    const int nh = blockIdx.z;
    const int n = nh >> 3, h = nh & 7;
    const int l0 = blockIdx.y * 64;
    const int s0 = blockIdx.x * 64;
    const int mbase = (L_ - 64) - l0 + s0;

#pragma unroll
    for (int t = 0; t < 8; t++) {
        int flat = tid + 256 * t;
        int r = flat >> 5, dd = flat & 31;
        float u = pu[h * 32 + dd], vb = pv[h * 32 + dd];
        float qval = qkv[(size_t)((l0 + r) * NB + n) * 768 + h * 32 + dd];
        qu[r][dd] = qval + u;
        qv[r][dd] = qval + vb;
        ks[r][dd] = qkv[(size_t)((s0 + r) * NB + n) * 768 + 256 + h * 32 + dd];
    }
#pragma unroll
    for (int t = 0; t < 16; t++) {
        int flat = tid + 256 * t;
        int r = flat >> 5, dd = flat & 31;
        int m = mbase + r;
        ps[r][dd] = (m < PM) ? p[(size_t)m * 256 + h * 32 + dd] : 0.f;
    }
    __syncthreads();

    const int trow = (tid >> 4) * 4;
    const int tcol = (tid & 15) * 4;
    const int pbase = 63 - trow + tcol;
    float ac[4][4] = {}, bd[4][4] = {};
#pragma unroll
    for (int dd = 0; dd < 32; dd++) {
        float ru[4], rv[4], rk[4], rp[7];
#pragma unroll
        for (int i = 0; i < 4; i++) { ru[i] = qu[trow + i][dd]; rv[i] = qv[trow + i][dd]; }
#pragma unroll
        for (int j = 0; j < 4; j++) rk[j] = ks[tcol + j][dd];
#pragma unroll
        for (int t = 0; t < 7; t++) rp[t] = ps[pbase + t - 3][dd];
#pragma unroll
        for (int i = 0; i < 4; i++)
#pragma unroll
            for (int j = 0; j < 4; j++) {
                ac[i][j] = fmaf(ru[i], rk[j], ac[i][j]);
                bd[i][j] = fmaf(rv[i], rp[j - i + 3], bd[i][j]);
            }
    }
    const float scal = 0.17677669529663687f;   // 1/sqrt(32)
    size_t base = (((size_t)nh) << 20) + (size_t)(l0 + trow) * L_ + s0 + tcol;
#pragma unroll
    for (int i = 0; i < 4; i++) {
        size_t rowb = base + (size_t)i * L_;
#pragma unroll
        for (int j = 0; j < 4; j++)
            total[rowb + j] = (ac[i][j] + bd[i][j]) * scal;
    }
}

// ---- fused proj_in + scores_out + softmax: one block per (n,l) row ------------
__global__ __launch_bounds__(256) void out_softmax_kernel(
    float* __restrict__ total, const float* __restrict__ asi,
    const float* __restrict__ projIn, const float* __restrict__ projOut,
    float* __restrict__ scores_out)
{
    __shared__ float ts[8][1028];
    __shared__ float pin[64], pout[64];
    __shared__ float red[8][8];
    const int tid = threadIdx.x;
    const int b = blockIdx.x;
    const int n = b >> 10, l = b & 1023;
    if (tid < 64) { pin[tid] = projIn[tid]; pout[tid] = projOut[tid]; }

#pragma unroll
    for (int h = 0; h < 8; h++) {
        float4 v = *(const float4*)(total + (((size_t)(n * 8 + h)) << 20)
                                          + ((size_t)l << 10) + tid * 4);
        *(float4*)&ts[h][tid * 4] = v;
    }
    __syncthreads();

    const int s = tid * 4;
    const size_t abase = ((size_t)n << 23) + ((size_t)l << 13) + ((size_t)s << 3);
    for (int js = 0; js < 4; js++) {
        float4 a0 = *(const float4*)(asi + abase + js * 8);
        float4 a1 = *(const float4*)(asi + abase + js * 8 + 4);
        float a[8] = {a0.x, a0.y, a0.z, a0.w, a1.x, a1.y, a1.z, a1.w};
        float tn8[8];
#pragma unroll
        for (int h = 0; h < 8; h++) {
            float t = ts[h][s + js];
#pragma unroll
            for (int g = 0; g < 8; g++) t = fmaf(a[g], pin[g * 8 + h], t);
            tn8[h] = t;
        }
        float o[8];
#pragma unroll
        for (int g = 0; g < 8; g++) {
            float sum = a[g];
#pragma unroll
            for (int h = 0; h < 8; h++) sum = fmaf(tn8[h], pout[h * 8 + g], sum);
            o[g] = sum;
        }
        *(float4*)(scores_out + abase + js * 8)     = make_float4(o[0], o[1], o[2], o[3]);
        *(float4*)(scores_out + abase + js * 8 + 4) = make_float4(o[4], o[5], o[6], o[7]);
#pragma unroll
        for (int h = 0; h < 8; h++) ts[h][s + js] = tn8[h];
    }

    float mh[8];
#pragma unroll
    for (int h = 0; h < 8; h++) {
        float m = fmaxf(fmaxf(ts[h][s], ts[h][s+1]), fmaxf(ts[h][s+2], ts[h][s+3]));
#pragma unroll
        for (int o = 16; o > 0; o >>= 1) m = fmaxf(m, __shfl_xor_sync(0xffffffffu, m, o));
        mh[h] = m;
    }
    if ((tid & 31) == 0)
#pragma unroll
        for (int h = 0; h < 8; h++) red[h][tid >> 5] = mh[h];
    __syncthreads();
#pragma unroll
    for (int h = 0; h < 8; h++) {
        float m = red[h][0];
#pragma unroll
        for (int w = 1; w < 8; w++) m = fmaxf(m, red[h][w]);
        mh[h] = m;
    }
    __syncthreads();

    float sh[8];
#pragma unroll
    for (int h = 0; h < 8; h++) {
        float s0 = 0.f;
#pragma unroll
        for (int js = 0; js < 4; js++) {
            float e = expf(ts[h][s + js] - mh[h]);
            ts[h][s + js] = e;
            s0 += e;
        }
#pragma unroll
        for (int o = 16; o > 0; o >>= 1) s0 += __shfl_xor_sync(0xffffffffu, s0, o);
        sh[h] = s0;
    }
    if ((tid & 31) == 0)
#pragma unroll
        for (int h = 0; h < 8; h++) red[h][tid >> 5] = sh[h];
    __syncthreads();
#pragma unroll
    for (int h = 0; h < 8; h++) {
        float ss = red[h][0] + red[h][1] + red[h][2] + red[h][3]
                 + red[h][4] + red[h][5] + red[h][6] + red[h][7];
        float inv = 1.f / ss;
        float4 o = make_float4(ts[h][s]*inv, ts[h][s+1]*inv, ts[h][s+2]*inv, ts[h][s+3]*inv);
        *(float4*)(total + (((size_t)(n * 8 + h)) << 20) + ((size_t)l << 10) + s) = o;
    }
}

// -------- ctx[l,n,h*32+d] = sum_s attn[n,h,l,s] * v[s,n,h,d] -------------------
__global__ __launch_bounds__(256) void av_kernel(
    const float* __restrict__ attn, const float* __restrict__ qkv,
    float* __restrict__ ctx)
{
    const int nh = blockIdx.y;
    const int n = nh >> 3, h = nh & 7;
    const int l0 = blockIdx.x * 64;
    __shared__ float As[64][65];
    __shared__ float Vs[64][33];
    const int tid = threadIdx.x;
    const int col = tid & 31;
    const int rg  = tid >> 5;
    float acc[8] = {};
    const float* Abase = attn + (((size_t)nh) << 20) + (((size_t)l0) << 10);
    for (int s0 = 0; s0 < 1024; s0 += 64) {
#pragma unroll
        for (int t = 0; t < 4; t++) {
            int f4 = tid + 256 * t;
            int r = f4 >> 4;
            int c4 = (f4 & 15) * 4;
            float4 v = *(const float4*)(Abase + (((size_t)r) << 10) + s0 + c4);
            As[r][c4] = v.x; As[r][c4 + 1] = v.y; As[r][c4 + 2] = v.z; As[r][c4 + 3] = v.w;
        }
#pragma unroll
        for (int t = 0; t < 8; t++) {
            int flat = tid + 256 * t;
            int r = flat >> 5, dd = flat & 31;
            Vs[r][dd] = qkv[(size_t)((s0 + r) * NB + n) * 768 + 512 + h * 32 + dd];
        }
        __syncthreads();
#pragma unroll
        for (int kk = 0; kk < 64; kk++) {
            float vv = Vs[kk][col];
#pragma unroll
            for (int i = 0; i < 8; i++)
                acc[i] = fmaf(As[rg * 8 + i][kk], vv, acc[i]);
        }
        __syncthreads();
    }
#pragma unroll
    for (int i = 0; i < 8; i++) {
        int l = l0 + rg * 8 + i;
        ctx[(size_t)(l * NB + n) * 256 + h * 32 + col] = acc[i];
    }
}

// -------- GLU + transpose to (n,c,l) ------------------------------------------
__global__ __launch_bounds__(256) void glu_kernel(
    const float* __restrict__ y, float* __restrict__ hglu)
{
    size_t idx = (size_t)blockIdx.x * 256 + threadIdx.x;
    int l = (int)(idx & 1023);
    int c = (int)((idx >> 10) & 511);
    int n = (int)(idx >> 19);
    size_t t = (size_t)l * NB + n;
    float a = y[t * 1024 + c];
    float b = y[t * 1024 + c + 512];
    hglu[idx] = a / (1.f + expf(-b));
}

// -------- depthwise conv(K=31) + bias + DoubleSwish ---------------------------
__global__ __launch_bounds__(256) void dwconv_kernel(
    const float* __restrict__ hglu, const float* __restrict__ w,
    const float* __restrict__ b, float* __restrict__ out)
{
    const int nc = blockIdx.x;
    const int c = nc & 511, n = nc >> 9;
    __shared__ float sm[L_ + 30];
    __shared__ float wc[KW];
    const float* row = hglu + (((size_t)nc) << 10);
    for (int i = threadIdx.x; i < L_ + 30; i += 256) {
        int l = i - 15;
        sm[i] = (l >= 0 && l < L_) ? row[l] : 0.f;
    }
    if (threadIdx.x < KW) wc[threadIdx.x] = w[c * KW + threadIdx.x];
    __syncthreads();
    const float bb = b[c];
    for (int l = threadIdx.x; l < L_; l += 256) {
        float s = bb;
#pragma unroll
        for (int k = 0; k < KW; k++) s = fmaf(sm[l + k], wc[k], s);
        out[(size_t)(l * NB + n) * E_ + c] = s / (1.f + expf(1.f - s));
    }
}

// -------- BasicNorm -> d_out ---------------------------------------------------
__global__ __launch_bounds__(128) void norm_kernel(
    const float* __restrict__ x, const float* __restrict__ leps,
    float* __restrict__ out)
{
    __shared__ float red[4];
    const size_t base = (size_t)blockIdx.x * 512;
    float4 v = ((const float4*)(x + base))[threadIdx.x];
    float ss = v.x * v.x + v.y * v.y + v.z * v.z + v.w * v.w;
#pragma unroll
    for (int o = 16; o > 0; o >>= 1) ss += __shfl_xor_sync(0xffffffffu, ss, o);
    if ((threadIdx.x & 31) == 0) red[threadIdx.x >> 5] = ss;
    __syncthreads();
    float tot = red[0] + red[1] + red[2] + red[3];
    float scale = rsqrtf(tot * (1.f / 512.f) + expf(leps[0]));
    ((float4*)(out + base))[threadIdx.x] =
        make_float4(v.x * scale, v.y * scale, v.z * scale, v.w * scale);
}

// ------------------------------- launcher -------------------------------------
extern "C" void kernel_launch(void* const* d_in, const int* in_sizes, int n_in,
                              void* d_out, int out_size)
{
    const float* src      = (const float*)d_in[0];
    const float* pos_emb  = (const float*)d_in[1];
    const float* asi      = (const float*)d_in[2];
    const float* w_in     = (const float*)d_in[3];
    const float* b_in     = (const float*)d_in[4];
    const float* w_pos    = (const float*)d_in[5];
    const float* pbu      = (const float*)d_in[6];
    const float* pbv      = (const float*)d_in[7];
    const float* projIn   = (const float*)d_in[8];
    const float* projOut  = (const float*)d_in[9];
    const float* w_out    = (const float*)d_in[10];
    const float* b_out    = (const float*)d_in[11];
    const float* w_ff1m   = (const float*)d_in[12];
    const float* b_ff1m   = (const float*)d_in[13];
    const float* w_ff2m   = (const float*)d_in[14];
    const float* b_ff2m   = (const float*)d_in[15];
    const float* w_ff1    = (const float*)d_in[16];
    const float* b_ff1    = (const float*)d_in[17];
    const float* w_ff2    = (const float*)d_in[18];
    const float* b_ff2    = (const float*)d_in[19];
    const float* w_pw1    = (const float*)d_in[20];
    const float* b_pw1    = (const float*)d_in[21];
    const float* w_dw     = (const float*)d_in[22];
    const float* b_dw     = (const float*)d_in[23];
    const float* w_pw2    = (const float*)d_in[24];
    const float* b_pw2    = (const float*)d_in[25];
    const float* leps     = (const float*)d_in[26];

    float* out        = (float*)d_out;
    float* out_scores = out + (size_t)TOK * E_;

    float *h1, *x, *qkv, *p, *total, *ctx, *x2, *y, *hglu, *hct, *x3, *x4;
    cudaGetSymbolAddress((void**)&h1,   g_h1);
    cudaGetSymbolAddress((void**)&x,    g_x);
    cudaGetSymbolAddress((void**)&qkv,  g_qkv);
    cudaGetSymbolAddress((void**)&p,    g_p);
    cudaGetSymbolAddress((void**)&total,g_total);
    cudaGetSymbolAddress((void**)&ctx,  g_ctx);
    cudaGetSymbolAddress((void**)&x2,   g_x2);
    cudaGetSymbolAddress((void**)&y,    g_y);
    cudaGetSymbolAddress((void**)&hglu, g_hglu);
    cudaGetSymbolAddress((void**)&hct,  g_hct);
    cudaGetSymbolAddress((void**)&x3,   g_x3);
    cudaGetSymbolAddress((void**)&x4,   g_x4);

    static bool attr_set = false;
    if (!attr_set) {
        cudaFuncSetAttribute(tgemm<0>, cudaFuncAttributeMaxDynamicSharedMemorySize, TG_SMEM);
        cudaFuncSetAttribute(tgemm<1>, cudaFuncAttributeMaxDynamicSharedMemorySize, TG_SMEM);
        cudaFuncSetAttribute(tgemm<2>, cudaFuncAttributeMaxDynamicSharedMemorySize, TG_SMEM);
        attr_set = true;
    }

    // macaron FFN
    tgemm<1><<<dim3(DFF_ / 128, TOK / 128), 256, TG_SMEM>>>(src, w_ff1m, b_ff1m, nullptr, h1, TOK, DFF_, E_);
    tgemm<2><<<dim3(E_ / 128, TOK / 128), 256, TG_SMEM>>>(h1, w_ff2m, b_ff2m, src, x, TOK, E_, DFF_);

    // attention inputs
    tgemm<0><<<dim3(768 / 128, TOK / 128), 256, TG_SMEM>>>(x, w_in, b_in, nullptr, qkv, TOK, 768, E_);
    tgemm<0><<<dim3(2, 16), 256, TG_SMEM>>>(pos_emb, w_pos, nullptr, nullptr, p, PM, 256, E_);

    // raw scores -> fused proj_in + scores_out + softmax -> AV
    scores_kernel<<<dim3(16, 16, 32), 256>>>(qkv, p, pbu, pbv, total);
    out_softmax_kernel<<<4096, 256>>>(total, asi, projIn, projOut, out_scores);
    av_kernel<<<dim3(16, 32), 256>>>(total, qkv, ctx);
    tgemm<2><<<dim3(E_ / 128, TOK / 128), 256, TG_SMEM>>>(ctx, w_out, b_out, x, x2, TOK, E_, E2_);

    // conv module
    tgemm<0><<<dim3(1024 / 128, TOK / 128), 256, TG_SMEM>>>(x2, w_pw1, b_pw1, nullptr, y, TOK, 1024, E_);
    glu_kernel<<<8192, 256>>>(y, hglu);
    dwconv_kernel<<<2048, 256>>>(hglu, w_dw, b_dw, hct);
    tgemm<2><<<dim3(E_ / 128, TOK / 128), 256, TG_SMEM>>>(hct, w_pw2, b_pw2, x2, x3, TOK, E_, E_);

    // final FFN + BasicNorm
    tgemm<1><<<dim3(DFF_ / 128, TOK / 128), 256, TG_SMEM>>>(x3, w_ff1, b_ff1, nullptr, h1, TOK, DFF_, E_);
    tgemm<2><<<dim3(E_ / 128, TOK / 128), 256, TG_SMEM>>>(h1, w_ff2, b_ff2, x3, x4, TOK, E_, DFF_);
    norm_kernel<<<TOK, 128>>>(x4, leps, out);
}

// round 7
// speedup vs baseline: 2.5011x; 1.1222x over previous
#include <cuda_runtime.h>
#include <math.h>
#include <stdint.h>

#define L_    1024
#define NB    4
#define E_    512
#define H_    8
#define D_    32
#define DFF_  2048
#define E2_   256
#define TOK   4096      // L*NB
#define PM    2047      // 2L-1
#define KW    31

// ---------------- scratch (static device globals; no allocation) -------------
__device__ float g_h1[(size_t)TOK * DFF_];
__device__ float g_x[(size_t)TOK * E_];
__device__ float g_qkv[(size_t)TOK * 768];
__device__ float g_p[(size_t)2048 * 256];
__device__ float g_total[(size_t)32 * 1024 * 1024];   // (N,H,L,S)
__device__ float g_ctx[(size_t)TOK * E2_];
__device__ float g_x2[(size_t)TOK * E_];
__device__ float g_y[(size_t)TOK * 1024];
__device__ float g_hglu[(size_t)NB * E_ * L_];
__device__ float g_hct[(size_t)TOK * E_];
__device__ float g_x3[(size_t)TOK * E_];
__device__ float g_x4[(size_t)TOK * E_];

// ---------------- tf32 / cp.async helpers -------------------------------------
__device__ __forceinline__ uint32_t f2tf(float f) {
    uint32_t u;
    asm("cvt.rna.tf32.f32 %0, %1;" : "=r"(u) : "f"(f));
    return u;
}
__device__ __forceinline__ void mma_tf32(float* c, const uint32_t* a, const uint32_t* b) {
    asm volatile(
        "mma.sync.aligned.m16n8k8.row.col.f32.tf32.tf32.f32 "
        "{%0,%1,%2,%3}, {%4,%5,%6,%7}, {%8,%9}, {%0,%1,%2,%3};"
        : "+f"(c[0]), "+f"(c[1]), "+f"(c[2]), "+f"(c[3])
        : "r"(a[0]), "r"(a[1]), "r"(a[2]), "r"(a[3]), "r"(b[0]), "r"(b[1]));
}
__device__ __forceinline__ void cp16(void* dst_smem, const void* src) {
    uint32_t d = (uint32_t)__cvta_generic_to_shared(dst_smem);
    asm volatile("cp.async.ca.shared.global [%0], [%1], 16;\n" :: "r"(d), "l"(src));
}

// ------------- cp.async double-buffered tf32 GEMM ----------------------------
// C = A(MxK) B(NxK)^T + bias (+epi). Nn % 128 == 0, Kk % 32 == 0.
// EPI: 0 = bias; 1 = bias + DoubleSwish; 2 = bias + residual add
#define TG_STRIDE 36
#define TG_BUFELT (128 * TG_STRIDE)
template <int EPI>
__global__ __launch_bounds__(256) void tgemm(
    const float* __restrict__ A, const float* __restrict__ B,
    const float* __restrict__ bias, const float* __restrict__ res,
    float* __restrict__ C, int M, int Nn, int Kk)
{
    extern __shared__ float smem[];
    float* Af = smem;                    // [2][128][36]
    float* Bf = smem + 2 * TG_BUFELT;    // [2][128][36]

    const int tid   = threadIdx.x;
    const int wid   = tid >> 5;
    const int lane  = tid & 31;
    const int grp   = lane >> 2;
    const int tig   = lane & 3;
    const int row0  = blockIdx.y * 128;
    const int col0  = blockIdx.x * 128;
    const int wm    = (wid >> 1) * 32;
    const int wn    = (wid & 1) * 64;

    float acc[2][8][4];
#pragma unroll
    for (int mt = 0; mt < 2; mt++)
#pragma unroll
        for (int nt = 0; nt < 8; nt++)
#pragma unroll
            for (int q = 0; q < 4; q++) acc[mt][nt][q] = 0.f;

    const int lrr = tid >> 3;
    const int lcc = (tid & 7) * 4;

#define LOADTILE(t, bf) {                                                       \
        const int kk0 = (t) * 32;                                               \
        _Pragma("unroll")                                                       \
        for (int i = 0; i < 4; i++) {                                           \
            int r = lrr + 32 * i;                                               \
            int ar = row0 + r; if (ar >= M) ar = M - 1;                         \
            cp16(&Af[(bf) * TG_BUFELT + r * TG_STRIDE + lcc],                   \
                 A + (size_t)ar * Kk + kk0 + lcc);                              \
            cp16(&Bf[(bf) * TG_BUFELT + r * TG_STRIDE + lcc],                   \
                 B + (size_t)(col0 + r) * Kk + kk0 + lcc);                      \
        }                                                                       \
        asm volatile("cp.async.commit_group;\n" ::); }

    const int ntile = Kk >> 5;
    LOADTILE(0, 0);
    int buf = 0;
    for (int t = 0; t < ntile; t++) {
        if (t + 1 < ntile) {
            LOADTILE(t + 1, buf ^ 1);
            asm volatile("cp.async.wait_group 1;\n" ::);
        } else {
            asm volatile("cp.async.wait_group 0;\n" ::);
        }
        __syncthreads();
        const float* Ab = Af + buf * TG_BUFELT;
        const float* Bb = Bf + buf * TG_BUFELT;
#pragma unroll
        for (int k8 = 0; k8 < 4; k8++) {
            const int kb = k8 * 8;
            uint32_t a[2][4], b[8][2];
#pragma unroll
            for (int mt = 0; mt < 2; mt++) {
                int mr = wm + mt * 16 + grp;
                a[mt][0] = f2tf(Ab[mr * TG_STRIDE + kb + tig]);
                a[mt][1] = f2tf(Ab[(mr + 8) * TG_STRIDE + kb + tig]);
                a[mt][2] = f2tf(Ab[mr * TG_STRIDE + kb + tig + 4]);
                a[mt][3] = f2tf(Ab[(mr + 8) * TG_STRIDE + kb + tig + 4]);
            }
#pragma unroll
            for (int nt = 0; nt < 8; nt++) {
                int nr = wn + nt * 8 + grp;
                b[nt][0] = f2tf(Bb[nr * TG_STRIDE + kb + tig]);
                b[nt][1] = f2tf(Bb[nr * TG_STRIDE + kb + tig + 4]);
            }
#pragma unroll
            for (int mt = 0; mt < 2; mt++)
#pragma unroll
                for (int nt = 0; nt < 8; nt++)
                    mma_tf32(acc[mt][nt], a[mt], b[nt]);
        }
        __syncthreads();
        buf ^= 1;
    }
#undef LOADTILE

#pragma unroll
    for (int mt = 0; mt < 2; mt++) {
        int rbase = row0 + wm + mt * 16 + grp;
#pragma unroll
        for (int nt = 0; nt < 8; nt++) {
            int col = col0 + wn + nt * 8 + tig * 2;
            float2 bb = make_float2(0.f, 0.f);
            if (bias) bb = *(const float2*)(bias + col);
#pragma unroll
            for (int half = 0; half < 2; half++) {
                int row = rbase + half * 8;
                if (row >= M) continue;
                float v0 = acc[mt][nt][half * 2 + 0] + bb.x;
                float v1 = acc[mt][nt][half * 2 + 1] + bb.y;
                if (EPI == 1) {
                    v0 = v0 / (1.f + expf(1.f - v0));
                    v1 = v1 / (1.f + expf(1.f - v1));
                }
                if (EPI == 2) {
                    float2 rr = *(const float2*)(res + (size_t)row * Nn + col);
                    v0 += rr.x; v1 += rr.y;
                }
                *(float2*)(C + (size_t)row * Nn + col) = make_float2(v0, v1);
            }
        }
    }
}
#define TG_SMEM (4 * TG_BUFELT * (int)sizeof(float))   // 73728 bytes

// -------- tf32-MMA scores: total = (QU·KS^T + relshift(QV·PS^T)) * scal -------
// Union smem: phase1 inputs QU/QV/KS/PS, phase2 outputs ACs/BDs.
#define SC_SMEM (12800 * (int)sizeof(float))   // 51200 bytes
__global__ __launch_bounds__(256) void scores_mma_kernel(
    const float* __restrict__ qkv, const float* __restrict__ p,
    const float* __restrict__ pu, const float* __restrict__ pv,
    float* __restrict__ total)
{
    extern __shared__ float sm[];
    float* QU  = sm;             // [64][36]
    float* QV  = sm + 2304;      // [64][36]
    float* KS  = sm + 4608;      // [64][36]
    float* PS  = sm + 6912;      // [128][36]
    float* ACs = sm;             // [64][68]  (phase 2)
    float* BDs = sm + 4352;      // [64][132] (phase 2)

    const int tid = threadIdx.x;
    const int nh = blockIdx.z;
    const int n = nh >> 3, h = nh & 7;
    const int l0 = blockIdx.y * 64;
    const int s0 = blockIdx.x * 64;
    const int mbase = (L_ - 64) - l0 + s0;

    // ---- phase 1: load inputs ----
#pragma unroll
    for (int it = 0; it < 2; it++) {
        int u = tid + it * 256;
        int r = u >> 3, d4 = (u & 7) * 4;
        float4 qf = *(const float4*)(qkv + (size_t)((l0 + r) * NB + n) * 768 + h * 32 + d4);
        float4 uu = *(const float4*)(pu + h * 32 + d4);
        float4 vv = *(const float4*)(pv + h * 32 + d4);
        QU[r * 36 + d4 + 0] = qf.x + uu.x; QU[r * 36 + d4 + 1] = qf.y + uu.y;
        QU[r * 36 + d4 + 2] = qf.z + uu.z; QU[r * 36 + d4 + 3] = qf.w + uu.w;
        QV[r * 36 + d4 + 0] = qf.x + vv.x; QV[r * 36 + d4 + 1] = qf.y + vv.y;
        QV[r * 36 + d4 + 2] = qf.z + vv.z; QV[r * 36 + d4 + 3] = qf.w + vv.w;
        float4 kf = *(const float4*)(qkv + (size_t)((s0 + r) * NB + n) * 768 + 256 + h * 32 + d4);
        KS[r * 36 + d4 + 0] = kf.x; KS[r * 36 + d4 + 1] = kf.y;
        KS[r * 36 + d4 + 2] = kf.z; KS[r * 36 + d4 + 3] = kf.w;
    }
#pragma unroll
    for (int it = 0; it < 4; it++) {
        int u = tid + it * 256;
        int r = u >> 3, d4 = (u & 7) * 4;
        int m = mbase + r;
        float4 pf = make_float4(0.f, 0.f, 0.f, 0.f);
        if (m < PM) pf = *(const float4*)(p + (size_t)m * 256 + h * 32 + d4);
        PS[r * 36 + d4 + 0] = pf.x; PS[r * 36 + d4 + 1] = pf.y;
        PS[r * 36 + d4 + 2] = pf.z; PS[r * 36 + d4 + 3] = pf.w;
    }
    __syncthreads();

    // ---- MMA phase ----
    const int wid = tid >> 5, lane = tid & 31;
    const int grp = lane >> 2, tig = lane & 3;
    const int wm = (wid >> 1) * 16;
    const int wnA = (wid & 1) * 32;
    const int wnB = (wid & 1) * 64;

    float acA[4][4] = {}, acB[8][4] = {};
#pragma unroll
    for (int k8 = 0; k8 < 4; k8++) {
        const int kb = k8 * 8;
        uint32_t aU[4], aV[4];
        aU[0] = f2tf(QU[(wm + grp) * 36 + kb + tig]);
        aU[1] = f2tf(QU[(wm + grp + 8) * 36 + kb + tig]);
        aU[2] = f2tf(QU[(wm + grp) * 36 + kb + tig + 4]);
        aU[3] = f2tf(QU[(wm + grp + 8) * 36 + kb + tig + 4]);
        aV[0] = f2tf(QV[(wm + grp) * 36 + kb + tig]);
        aV[1] = f2tf(QV[(wm + grp + 8) * 36 + kb + tig]);
        aV[2] = f2tf(QV[(wm + grp) * 36 + kb + tig + 4]);
        aV[3] = f2tf(QV[(wm + grp + 8) * 36 + kb + tig + 4]);
#pragma unroll
        for (int nt = 0; nt < 4; nt++) {
            int nr = wnA + nt * 8 + grp;
            uint32_t b[2] = { f2tf(KS[nr * 36 + kb + tig]), f2tf(KS[nr * 36 + kb + tig + 4]) };
            mma_tf32(acA[nt], aU, b);
        }
#pragma unroll
        for (int nt = 0; nt < 8; nt++) {
            int nr = wnB + nt * 8 + grp;
            uint32_t b[2] = { f2tf(PS[nr * 36 + kb + tig]), f2tf(PS[nr * 36 + kb + tig + 4]) };
            mma_tf32(acB[nt], aV, b);
        }
    }
    __syncthreads();   // inputs no longer needed; smem reused for outputs

    // ---- store accumulators to smem ----
#pragma unroll
    for (int nt = 0; nt < 4; nt++) {
        int col = wnA + nt * 8 + tig * 2;
        *(float2*)&ACs[(wm + grp) * 68 + col]     = make_float2(acA[nt][0], acA[nt][1]);
        *(float2*)&ACs[(wm + grp + 8) * 68 + col] = make_float2(acA[nt][2], acA[nt][3]);
    }
#pragma unroll
    for (int nt = 0; nt < 8; nt++) {
        int col = wnB + nt * 8 + tig * 2;
        *(float2*)&BDs[(wm + grp) * 132 + col]     = make_float2(acB[nt][0], acB[nt][1]);
        *(float2*)&BDs[(wm + grp + 8) * 132 + col] = make_float2(acB[nt][2], acB[nt][3]);
    }
    __syncthreads();

    // ---- combine: total[i][j] = (AC[i][j] + BD[i][63-i+j]) * scal ----
    const float scal = 0.17677669529663687f;   // 1/sqrt(32)
    const int cc = (tid & 15) * 4;
    const int rb = tid >> 4;
#pragma unroll
    for (int it = 0; it < 4; it++) {
        int r = rb + it * 16;
        int off = 63 - r + cc;
        float4 o;
        o.x = (ACs[r * 68 + cc + 0] + BDs[r * 132 + off + 0]) * scal;
        o.y = (ACs[r * 68 + cc + 1] + BDs[r * 132 + off + 1]) * scal;
        o.z = (ACs[r * 68 + cc + 2] + BDs[r * 132 + off + 2]) * scal;
        o.w = (ACs[r * 68 + cc + 3] + BDs[r * 132 + off + 3]) * scal;
        *(float4*)(total + (((size_t)nh) << 20) + (size_t)(l0 + r) * L_ + s0 + cc) = o;
    }
}

// ---- fused proj_in + scores_out + softmax: one block per (n,l) row ------------
__global__ __launch_bounds__(256) void out_softmax_kernel(
    float* __restrict__ total, const float* __restrict__ asi,
    const float* __restrict__ projIn, const float* __restrict__ projOut,
    float* __restrict__ scores_out)
{
    __shared__ float ts[8][1028];
    __shared__ float pin[64], pout[64];
    __shared__ float red[8][8];
    const int tid = threadIdx.x;
    const int b = blockIdx.x;
    const int n = b >> 10, l = b & 1023;
    if (tid < 64) { pin[tid] = projIn[tid]; pout[tid] = projOut[tid]; }

#pragma unroll
    for (int h = 0; h < 8; h++) {
        float4 v = *(const float4*)(total + (((size_t)(n * 8 + h)) << 20)
                                          + ((size_t)l << 10) + tid * 4);
        *(float4*)&ts[h][tid * 4] = v;
    }
    __syncthreads();

    const int s = tid * 4;
    const size_t abase = ((size_t)n << 23) + ((size_t)l << 13) + ((size_t)s << 3);
    for (int js = 0; js < 4; js++) {
        float4 a0 = *(const float4*)(asi + abase + js * 8);
        float4 a1 = *(const float4*)(asi + abase + js * 8 + 4);
        float a[8] = {a0.x, a0.y, a0.z, a0.w, a1.x, a1.y, a1.z, a1.w};
        float tn8[8];
#pragma unroll
        for (int h = 0; h < 8; h++) {
            float t = ts[h][s + js];
#pragma unroll
            for (int g = 0; g < 8; g++) t = fmaf(a[g], pin[g * 8 + h], t);
            tn8[h] = t;
        }
        float o[8];
#pragma unroll
        for (int g = 0; g < 8; g++) {
            float sum = a[g];
#pragma unroll
            for (int h = 0; h < 8; h++) sum = fmaf(tn8[h], pout[h * 8 + g], sum);
            o[g] = sum;
        }
        *(float4*)(scores_out + abase + js * 8)     = make_float4(o[0], o[1], o[2], o[3]);
        *(float4*)(scores_out + abase + js * 8 + 4) = make_float4(o[4], o[5], o[6], o[7]);
#pragma unroll
        for (int h = 0; h < 8; h++) ts[h][s + js] = tn8[h];
    }

    float mh[8];
#pragma unroll
    for (int h = 0; h < 8; h++) {
        float m = fmaxf(fmaxf(ts[h][s], ts[h][s+1]), fmaxf(ts[h][s+2], ts[h][s+3]));
#pragma unroll
        for (int o = 16; o > 0; o >>= 1) m = fmaxf(m, __shfl_xor_sync(0xffffffffu, m, o));
        mh[h] = m;
    }
    if ((tid & 31) == 0)
#pragma unroll
        for (int h = 0; h < 8; h++) red[h][tid >> 5] = mh[h];
    __syncthreads();
#pragma unroll
    for (int h = 0; h < 8; h++) {
        float m = red[h][0];
#pragma unroll
        for (int w = 1; w < 8; w++) m = fmaxf(m, red[h][w]);
        mh[h] = m;
    }
    __syncthreads();

    float sh[8];
#pragma unroll
    for (int h = 0; h < 8; h++) {
        float s0 = 0.f;
#pragma unroll
        for (int js = 0; js < 4; js++) {
            float e = expf(ts[h][s + js] - mh[h]);
            ts[h][s + js] = e;
            s0 += e;
        }
#pragma unroll
        for (int o = 16; o > 0; o >>= 1) s0 += __shfl_xor_sync(0xffffffffu, s0, o);
        sh[h] = s0;
    }
    if ((tid & 31) == 0)
#pragma unroll
        for (int h = 0; h < 8; h++) red[h][tid >> 5] = sh[h];
    __syncthreads();
#pragma unroll
    for (int h = 0; h < 8; h++) {
        float ss = red[h][0] + red[h][1] + red[h][2] + red[h][3]
                 + red[h][4] + red[h][5] + red[h][6] + red[h][7];
        float inv = 1.f / ss;
        float4 o = make_float4(ts[h][s]*inv, ts[h][s+1]*inv, ts[h][s+2]*inv, ts[h][s+3]*inv);
        *(float4*)(total + (((size_t)(n * 8 + h)) << 20) + ((size_t)l << 10) + s) = o;
    }
}

// -------- ctx[l,n,h*32+d] = sum_s attn[n,h,l,s] * v[s,n,h,d] -------------------
__global__ __launch_bounds__(256) void av_kernel(
    const float* __restrict__ attn, const float* __restrict__ qkv,
    float* __restrict__ ctx)
{
    const int nh = blockIdx.y;
    const int n = nh >> 3, h = nh & 7;
    const int l0 = blockIdx.x * 64;
    __shared__ float As[64][65];
    __shared__ float Vs[64][33];
    const int tid = threadIdx.x;
    const int col = tid & 31;
    const int rg  = tid >> 5;
    float acc[8] = {};
    const float* Abase = attn + (((size_t)nh) << 20) + (((size_t)l0) << 10);
    for (int s0 = 0; s0 < 1024; s0 += 64) {
#pragma unroll
        for (int t = 0; t < 4; t++) {
            int f4 = tid + 256 * t;
            int r = f4 >> 4;
            int c4 = (f4 & 15) * 4;
            float4 v = *(const float4*)(Abase + (((size_t)r) << 10) + s0 + c4);
            As[r][c4] = v.x; As[r][c4 + 1] = v.y; As[r][c4 + 2] = v.z; As[r][c4 + 3] = v.w;
        }
#pragma unroll
        for (int t = 0; t < 8; t++) {
            int flat = tid + 256 * t;
            int r = flat >> 5, dd = flat & 31;
            Vs[r][dd] = qkv[(size_t)((s0 + r) * NB + n) * 768 + 512 + h * 32 + dd];
        }
        __syncthreads();
#pragma unroll
        for (int kk = 0; kk < 64; kk++) {
            float vv = Vs[kk][col];
#pragma unroll
            for (int i = 0; i < 8; i++)
                acc[i] = fmaf(As[rg * 8 + i][kk], vv, acc[i]);
        }
        __syncthreads();
    }
#pragma unroll
    for (int i = 0; i < 8; i++) {
        int l = l0 + rg * 8 + i;
        ctx[(size_t)(l * NB + n) * 256 + h * 32 + col] = acc[i];
    }
}

// -------- GLU with 32x32 smem transpose: y(l,n,:) -> hglu(n,c,l) ---------------
__global__ __launch_bounds__(256) void glu_t_kernel(
    const float* __restrict__ y, float* __restrict__ hglu)
{
    __shared__ float sm[32][33];
    const int l0 = blockIdx.x * 32, c0 = blockIdx.y * 32, n = blockIdx.z;
    const int li = threadIdx.x >> 3;
    const int c4 = (threadIdx.x & 7) * 4;
    size_t t = (size_t)(l0 + li) * NB + n;
    float4 a = *(const float4*)(y + t * 1024 + c0 + c4);
    float4 b = *(const float4*)(y + t * 1024 + c0 + c4 + 512);
    sm[c4 + 0][li] = a.x / (1.f + expf(-b.x));
    sm[c4 + 1][li] = a.y / (1.f + expf(-b.y));
    sm[c4 + 2][li] = a.z / (1.f + expf(-b.z));
    sm[c4 + 3][li] = a.w / (1.f + expf(-b.w));
    __syncthreads();
    const int c = threadIdx.x >> 3;
    const int l4 = (threadIdx.x & 7) * 4;
    float4 o = make_float4(sm[c][l4], sm[c][l4 + 1], sm[c][l4 + 2], sm[c][l4 + 3]);
    *(float4*)(hglu + (((size_t)(n * 512 + c0 + c)) << 10) + l0 + l4) = o;
}

// -------- depthwise conv(K=31) + bias + DoubleSwish, coalesced writes ---------
// block: (n, 32 channels, 128 l). in smem tile [32][161], weights [32][33].
__global__ __launch_bounds__(256) void dwconv_kernel(
    const float* __restrict__ hglu, const float* __restrict__ w,
    const float* __restrict__ b, float* __restrict__ out)
{
    __shared__ float in_s[32 * 161];
    __shared__ float w_s[32 * 33];
    const int l0 = blockIdx.x * 128;
    const int c0 = blockIdx.y * 32;
    const int n  = blockIdx.z;

    for (int idx = threadIdx.x; idx < 32 * 160; idx += 256) {
        int row = idx / 160, col = idx % 160;
        int gl = l0 + col - 15;
        float v = 0.f;
        if (col < 158 && gl >= 0 && gl < L_)
            v = hglu[(((size_t)(n * 512 + c0 + row)) << 10) + gl];
        in_s[row * 161 + col] = v;
    }
    for (int idx = threadIdx.x; idx < 32 * KW; idx += 256) {
        int c = idx / KW, k = idx % KW;
        w_s[c * 33 + k] = w[(c0 + c) * KW + k];
    }
    __syncthreads();

    const int ci = threadIdx.x & 31;
    const int lq = threadIdx.x >> 5;
    const float bb = b[c0 + ci];
#pragma unroll
    for (int lt = 0; lt < 16; lt++) {
        int ll = lt * 8 + lq;
        float s = bb;
#pragma unroll
        for (int k = 0; k < KW; k++)
            s = fmaf(in_s[ci * 161 + ll + k], w_s[ci * 33 + k], s);
        float v = s / (1.f + expf(1.f - s));
        out[(((size_t)((l0 + ll) * NB + n)) << 9) + c0 + ci] = v;
    }
}

// -------- BasicNorm -> d_out ---------------------------------------------------
__global__ __launch_bounds__(128) void norm_kernel(
    const float* __restrict__ x, const float* __restrict__ leps,
    float* __restrict__ out)
{
    __shared__ float red[4];
    const size_t base = (size_t)blockIdx.x * 512;
    float4 v = ((const float4*)(x + base))[threadIdx.x];
    float ss = v.x * v.x + v.y * v.y + v.z * v.z + v.w * v.w;
#pragma unroll
    for (int o = 16; o > 0; o >>= 1) ss += __shfl_xor_sync(0xffffffffu, ss, o);
    if ((threadIdx.x & 31) == 0) red[threadIdx.x >> 5] = ss;
    __syncthreads();
    float tot = red[0] + red[1] + red[2] + red[3];
    float scale = rsqrtf(tot * (1.f / 512.f) + expf(leps[0]));
    ((float4*)(out + base))[threadIdx.x] =
        make_float4(v.x * scale, v.y * scale, v.z * scale, v.w * scale);
}

// ------------------------------- launcher -------------------------------------
extern "C" void kernel_launch(void* const* d_in, const int* in_sizes, int n_in,
                              void* d_out, int out_size)
{
    const float* src      = (const float*)d_in[0];
    const float* pos_emb  = (const float*)d_in[1];
    const float* asi      = (const float*)d_in[2];
    const float* w_in     = (const float*)d_in[3];
    const float* b_in     = (const float*)d_in[4];
    const float* w_pos    = (const float*)d_in[5];
    const float* pbu      = (const float*)d_in[6];
    const float* pbv      = (const float*)d_in[7];
    const float* projIn   = (const float*)d_in[8];
    const float* projOut  = (const float*)d_in[9];
    const float* w_out    = (const float*)d_in[10];
    const float* b_out    = (const float*)d_in[11];
    const float* w_ff1m   = (const float*)d_in[12];
    const float* b_ff1m   = (const float*)d_in[13];
    const float* w_ff2m   = (const float*)d_in[14];
    const float* b_ff2m   = (const float*)d_in[15];
    const float* w_ff1    = (const float*)d_in[16];
    const float* b_ff1    = (const float*)d_in[17];
    const float* w_ff2    = (const float*)d_in[18];
    const float* b_ff2    = (const float*)d_in[19];
    const float* w_pw1    = (const float*)d_in[20];
    const float* b_pw1    = (const float*)d_in[21];
    const float* w_dw     = (const float*)d_in[22];
    const float* b_dw     = (const float*)d_in[23];
    const float* w_pw2    = (const float*)d_in[24];
    const float* b_pw2    = (const float*)d_in[25];
    const float* leps     = (const float*)d_in[26];

    float* out        = (float*)d_out;
    float* out_scores = out + (size_t)TOK * E_;

    float *h1, *x, *qkv, *p, *total, *ctx, *x2, *y, *hglu, *hct, *x3, *x4;
    cudaGetSymbolAddress((void**)&h1,   g_h1);
    cudaGetSymbolAddress((void**)&x,    g_x);
    cudaGetSymbolAddress((void**)&qkv,  g_qkv);
    cudaGetSymbolAddress((void**)&p,    g_p);
    cudaGetSymbolAddress((void**)&total,g_total);
    cudaGetSymbolAddress((void**)&ctx,  g_ctx);
    cudaGetSymbolAddress((void**)&x2,   g_x2);
    cudaGetSymbolAddress((void**)&y,    g_y);
    cudaGetSymbolAddress((void**)&hglu, g_hglu);
    cudaGetSymbolAddress((void**)&hct,  g_hct);
    cudaGetSymbolAddress((void**)&x3,   g_x3);
    cudaGetSymbolAddress((void**)&x4,   g_x4);

    static bool attr_set = false;
    if (!attr_set) {
        cudaFuncSetAttribute(tgemm<0>, cudaFuncAttributeMaxDynamicSharedMemorySize, TG_SMEM);
        cudaFuncSetAttribute(tgemm<1>, cudaFuncAttributeMaxDynamicSharedMemorySize, TG_SMEM);
        cudaFuncSetAttribute(tgemm<2>, cudaFuncAttributeMaxDynamicSharedMemorySize, TG_SMEM);
        cudaFuncSetAttribute(scores_mma_kernel, cudaFuncAttributeMaxDynamicSharedMemorySize, SC_SMEM);
        attr_set = true;
    }

    // macaron FFN
    tgemm<1><<<dim3(DFF_ / 128, TOK / 128), 256, TG_SMEM>>>(src, w_ff1m, b_ff1m, nullptr, h1, TOK, DFF_, E_);
    tgemm<2><<<dim3(E_ / 128, TOK / 128), 256, TG_SMEM>>>(h1, w_ff2m, b_ff2m, src, x, TOK, E_, DFF_);

    // attention inputs
    tgemm<0><<<dim3(768 / 128, TOK / 128), 256, TG_SMEM>>>(x, w_in, b_in, nullptr, qkv, TOK, 768, E_);
    tgemm<0><<<dim3(2, 16), 256, TG_SMEM>>>(pos_emb, w_pos, nullptr, nullptr, p, PM, 256, E_);

    // raw scores (tf32 MMA) -> fused proj_in + scores_out + softmax -> AV
    scores_mma_kernel<<<dim3(16, 16, 32), 256, SC_SMEM>>>(qkv, p, pbu, pbv, total);
    out_softmax_kernel<<<4096, 256>>>(total, asi, projIn, projOut, out_scores);
    av_kernel<<<dim3(16, 32), 256>>>(total, qkv, ctx);
    tgemm<2><<<dim3(E_ / 128, TOK / 128), 256, TG_SMEM>>>(ctx, w_out, b_out, x, x2, TOK, E_, E2_);

    // conv module
    tgemm<0><<<dim3(1024 / 128, TOK / 128), 256, TG_SMEM>>>(x2, w_pw1, b_pw1, nullptr, y, TOK, 1024, E_);
    glu_t_kernel<<<dim3(32, 16, NB), 256>>>(y, hglu);
    dwconv_kernel<<<dim3(8, 16, NB), 256>>>(hglu, w_dw, b_dw, hct);
    tgemm<2><<<dim3(E_ / 128, TOK / 128), 256, TG_SMEM>>>(hct, w_pw2, b_pw2, x2, x3, TOK, E_, E_);

    // final FFN + BasicNorm
    tgemm<1><<<dim3(DFF_ / 128, TOK / 128), 256, TG_SMEM>>>(x3, w_ff1, b_ff1, nullptr, h1, TOK, DFF_, E_);
    tgemm<2><<<dim3(E_ / 128, TOK / 128), 256, TG_SMEM>>>(h1, w_ff2, b_ff2, x3, x4, TOK, E_, DFF_);
    norm_kernel<<<TOK, 128>>>(x4, leps, out);
}

// round 8
// speedup vs baseline: 2.6342x; 1.0532x over previous
#include <cuda_runtime.h>
#include <math.h>
#include <stdint.h>

#define L_    1024
#define NB    4
#define E_    512
#define H_    8
#define D_    32
#define DFF_  2048
#define E2_   256
#define TOK   4096      // L*NB
#define PM    2047      // 2L-1
#define KW    31

// ---------------- scratch (static device globals; no allocation) -------------
__device__ float g_h1[(size_t)TOK * DFF_];
__device__ float g_x[(size_t)TOK * E_];
__device__ float g_qkv[(size_t)TOK * 768];
__device__ float g_p[(size_t)2048 * 256];
__device__ float g_total[(size_t)32 * 1024 * 1024];   // (N,H,L,S)
__device__ float g_ctx[(size_t)TOK * E2_];
__device__ float g_x2[(size_t)TOK * E_];
__device__ float g_y[(size_t)TOK * 1024];
__device__ float g_hglu[(size_t)NB * E_ * L_];
__device__ float g_hct[(size_t)TOK * E_];
__device__ float g_x3[(size_t)TOK * E_];
__device__ float g_x4[(size_t)TOK * E_];
__device__ float g_wtf[(size_t)5636096];              // tf32-rounded weights

// tf32 weight scratch offsets
#define OFF_FF1M 0
#define OFF_FF2M 1048576
#define OFF_IN   2097152
#define OFF_POS  2490368
#define OFF_OUT  2621440
#define OFF_PW1  2752512
#define OFF_PW2  3276800
#define OFF_FF1  3538944
#define OFF_FF2  4587520

// ---------------- tf32 / cp.async helpers -------------------------------------
__device__ __forceinline__ uint32_t f2tf(float f) {
    uint32_t u;
    asm("cvt.rna.tf32.f32 %0, %1;" : "=r"(u) : "f"(f));
    return u;
}
__device__ __forceinline__ void mma_tf32(float* c, const uint32_t* a, const uint32_t* b) {
    asm volatile(
        "mma.sync.aligned.m16n8k8.row.col.f32.tf32.tf32.f32 "
        "{%0,%1,%2,%3}, {%4,%5,%6,%7}, {%8,%9}, {%0,%1,%2,%3};"
        : "+f"(c[0]), "+f"(c[1]), "+f"(c[2]), "+f"(c[3])
        : "r"(a[0]), "r"(a[1]), "r"(a[2]), "r"(a[3]), "r"(b[0]), "r"(b[1]));
}
__device__ __forceinline__ void cp16(void* dst_smem, const void* src) {
    uint32_t d = (uint32_t)__cvta_generic_to_shared(dst_smem);
    asm volatile("cp.async.ca.shared.global [%0], [%1], 16;\n" :: "r"(d), "l"(src));
}

// -------- prepass: round 9 weight matrices to tf32 (RNA) into g_wtf ------------
struct CvtArgs {
    const float* src[9];
    int dstoff[9];
    int n4[9];
};
__global__ __launch_bounds__(256) void cvtw_kernel(CvtArgs args) {
    const int wi = blockIdx.y;
    const int idx = blockIdx.x * 256 + threadIdx.x;
    if (idx >= args.n4[wi]) return;
    float4 v = *(const float4*)(args.src[wi] + (size_t)idx * 4);
    uint4 o;
    o.x = f2tf(v.x); o.y = f2tf(v.y); o.z = f2tf(v.z); o.w = f2tf(v.w);
    *(uint4*)(g_wtf + args.dstoff[wi] + (size_t)idx * 4) = o;
}

// ------------- cp.async double-buffered tf32 GEMM (4 warps, 64x64 warptile) ---
// C = A(MxK) B(NxK)^T + bias (+epi). Nn % 128 == 0, Kk % 32 == 0.
// B must be pre-rounded to tf32 (g_wtf). A converted at fragment load.
// EPI: 0 = bias; 1 = bias + DoubleSwish; 2 = bias + residual add
#define TG_STRIDE 36
#define TG_BUFELT (128 * TG_STRIDE)
template <int EPI>
__global__ __launch_bounds__(128) void tgemm(
    const float* __restrict__ A, const float* __restrict__ B,
    const float* __restrict__ bias, const float* __restrict__ res,
    float* __restrict__ C, int M, int Nn, int Kk)
{
    extern __shared__ float smem[];
    float* Af = smem;                    // [2][128][36]
    float* Bf = smem + 2 * TG_BUFELT;    // [2][128][36]

    const int tid   = threadIdx.x;
    const int wid   = tid >> 5;          // 0..3
    const int lane  = tid & 31;
    const int grp   = lane >> 2;
    const int tig   = lane & 3;
    const int row0  = blockIdx.y * 128;
    const int col0  = blockIdx.x * 128;
    const int wm    = (wid >> 1) * 64;   // 0 or 64
    const int wn    = (wid & 1) * 64;    // 0 or 64

    float acc[4][8][4];
#pragma unroll
    for (int mt = 0; mt < 4; mt++)
#pragma unroll
        for (int nt = 0; nt < 8; nt++)
#pragma unroll
            for (int q = 0; q < 4; q++) acc[mt][nt][q] = 0.f;

    const int lrr = tid >> 3;            // 0..15
    const int lcc = (tid & 7) * 4;       // 0..28

#define LOADTILE(t, bf) {                                                       \
        const int kk0 = (t) * 32;                                               \
        _Pragma("unroll")                                                       \
        for (int i = 0; i < 8; i++) {                                           \
            int r = lrr + 16 * i;                                               \
            int ar = row0 + r; if (ar >= M) ar = M - 1;                         \
            cp16(&Af[(bf) * TG_BUFELT + r * TG_STRIDE + lcc],                   \
                 A + (size_t)ar * Kk + kk0 + lcc);                              \
            cp16(&Bf[(bf) * TG_BUFELT + r * TG_STRIDE + lcc],                   \
                 B + (size_t)(col0 + r) * Kk + kk0 + lcc);                      \
        }                                                                       \
        asm volatile("cp.async.commit_group;\n" ::); }

    const int ntile = Kk >> 5;
    LOADTILE(0, 0);
    int buf = 0;
    for (int t = 0; t < ntile; t++) {
        if (t + 1 < ntile) {
            LOADTILE(t + 1, buf ^ 1);
            asm volatile("cp.async.wait_group 1;\n" ::);
        } else {
            asm volatile("cp.async.wait_group 0;\n" ::);
        }
        __syncthreads();
        const float* Ab = Af + buf * TG_BUFELT;
        const float* Bb = Bf + buf * TG_BUFELT;
#pragma unroll
        for (int k8 = 0; k8 < 4; k8++) {
            const int kb = k8 * 8;
            uint32_t a[4][4], b[8][2];
#pragma unroll
            for (int mt = 0; mt < 4; mt++) {
                int mr = wm + mt * 16 + grp;
                a[mt][0] = f2tf(Ab[mr * TG_STRIDE + kb + tig]);
                a[mt][1] = f2tf(Ab[(mr + 8) * TG_STRIDE + kb + tig]);
                a[mt][2] = f2tf(Ab[mr * TG_STRIDE + kb + tig + 4]);
                a[mt][3] = f2tf(Ab[(mr + 8) * TG_STRIDE + kb + tig + 4]);
            }
#pragma unroll
            for (int nt = 0; nt < 8; nt++) {
                int nr = wn + nt * 8 + grp;
                b[nt][0] = __float_as_uint(Bb[nr * TG_STRIDE + kb + tig]);
                b[nt][1] = __float_as_uint(Bb[nr * TG_STRIDE + kb + tig + 4]);
            }
#pragma unroll
            for (int mt = 0; mt < 4; mt++)
#pragma unroll
                for (int nt = 0; nt < 8; nt++)
                    mma_tf32(acc[mt][nt], a[mt], b[nt]);
        }
        __syncthreads();
        buf ^= 1;
    }
#undef LOADTILE

#pragma unroll
    for (int mt = 0; mt < 4; mt++) {
        int rbase = row0 + wm + mt * 16 + grp;
#pragma unroll
        for (int nt = 0; nt < 8; nt++) {
            int col = col0 + wn + nt * 8 + tig * 2;
            float2 bb = make_float2(0.f, 0.f);
            if (bias) bb = *(const float2*)(bias + col);
#pragma unroll
            for (int half = 0; half < 2; half++) {
                int row = rbase + half * 8;
                if (row >= M) continue;
                float v0 = acc[mt][nt][half * 2 + 0] + bb.x;
                float v1 = acc[mt][nt][half * 2 + 1] + bb.y;
                if (EPI == 1) {
                    v0 = v0 / (1.f + expf(1.f - v0));
                    v1 = v1 / (1.f + expf(1.f - v1));
                }
                if (EPI == 2) {
                    float2 rr = *(const float2*)(res + (size_t)row * Nn + col);
                    v0 += rr.x; v1 += rr.y;
                }
                *(float2*)(C + (size_t)row * Nn + col) = make_float2(v0, v1);
            }
        }
    }
}
#define TG_SMEM (4 * TG_BUFELT * (int)sizeof(float))   // 73728 bytes

// -------- tf32-MMA scores: total = (QU·KS^T + relshift(QV·PS^T)) * scal -------
#define SC_SMEM (12800 * (int)sizeof(float))   // 51200 bytes
__global__ __launch_bounds__(256) void scores_mma_kernel(
    const float* __restrict__ qkv, const float* __restrict__ p,
    const float* __restrict__ pu, const float* __restrict__ pv,
    float* __restrict__ total)
{
    extern __shared__ float sm[];
    float* QU  = sm;             // [64][36]
    float* QV  = sm + 2304;      // [64][36]
    float* KS  = sm + 4608;      // [64][36]
    float* PS  = sm + 6912;      // [128][36]
    float* ACs = sm;             // [64][68]  (phase 2)
    float* BDs = sm + 4352;      // [64][132] (phase 2)

    const int tid = threadIdx.x;
    const int nh = blockIdx.z;
    const int n = nh >> 3, h = nh & 7;
    const int l0 = blockIdx.y * 64;
    const int s0 = blockIdx.x * 64;
    const int mbase = (L_ - 64) - l0 + s0;

#pragma unroll
    for (int it = 0; it < 2; it++) {
        int u = tid + it * 256;
        int r = u >> 3, d4 = (u & 7) * 4;
        float4 qf = *(const float4*)(qkv + (size_t)((l0 + r) * NB + n) * 768 + h * 32 + d4);
        float4 uu = *(const float4*)(pu + h * 32 + d4);
        float4 vv = *(const float4*)(pv + h * 32 + d4);
        QU[r * 36 + d4 + 0] = qf.x + uu.x; QU[r * 36 + d4 + 1] = qf.y + uu.y;
        QU[r * 36 + d4 + 2] = qf.z + uu.z; QU[r * 36 + d4 + 3] = qf.w + uu.w;
        QV[r * 36 + d4 + 0] = qf.x + vv.x; QV[r * 36 + d4 + 1] = qf.y + vv.y;
        QV[r * 36 + d4 + 2] = qf.z + vv.z; QV[r * 36 + d4 + 3] = qf.w + vv.w;
        float4 kf = *(const float4*)(qkv + (size_t)((s0 + r) * NB + n) * 768 + 256 + h * 32 + d4);
        KS[r * 36 + d4 + 0] = kf.x; KS[r * 36 + d4 + 1] = kf.y;
        KS[r * 36 + d4 + 2] = kf.z; KS[r * 36 + d4 + 3] = kf.w;
    }
#pragma unroll
    for (int it = 0; it < 4; it++) {
        int u = tid + it * 256;
        int r = u >> 3, d4 = (u & 7) * 4;
        int m = mbase + r;
        float4 pf = make_float4(0.f, 0.f, 0.f, 0.f);
        if (m < PM) pf = *(const float4*)(p + (size_t)m * 256 + h * 32 + d4);
        PS[r * 36 + d4 + 0] = pf.x; PS[r * 36 + d4 + 1] = pf.y;
        PS[r * 36 + d4 + 2] = pf.z; PS[r * 36 + d4 + 3] = pf.w;
    }
    __syncthreads();

    const int wid = tid >> 5, lane = tid & 31;
    const int grp = lane >> 2, tig = lane & 3;
    const int wm = (wid >> 1) * 16;
    const int wnA = (wid & 1) * 32;
    const int wnB = (wid & 1) * 64;

    float acA[4][4] = {}, acB[8][4] = {};
#pragma unroll
    for (int k8 = 0; k8 < 4; k8++) {
        const int kb = k8 * 8;
        uint32_t aU[4], aV[4];
        aU[0] = f2tf(QU[(wm + grp) * 36 + kb + tig]);
        aU[1] = f2tf(QU[(wm + grp + 8) * 36 + kb + tig]);
        aU[2] = f2tf(QU[(wm + grp) * 36 + kb + tig + 4]);
        aU[3] = f2tf(QU[(wm + grp + 8) * 36 + kb + tig + 4]);
        aV[0] = f2tf(QV[(wm + grp) * 36 + kb + tig]);
        aV[1] = f2tf(QV[(wm + grp + 8) * 36 + kb + tig]);
        aV[2] = f2tf(QV[(wm + grp) * 36 + kb + tig + 4]);
        aV[3] = f2tf(QV[(wm + grp + 8) * 36 + kb + tig + 4]);
#pragma unroll
        for (int nt = 0; nt < 4; nt++) {
            int nr = wnA + nt * 8 + grp;
            uint32_t b[2] = { f2tf(KS[nr * 36 + kb + tig]), f2tf(KS[nr * 36 + kb + tig + 4]) };
            mma_tf32(acA[nt], aU, b);
        }
#pragma unroll
        for (int nt = 0; nt < 8; nt++) {
            int nr = wnB + nt * 8 + grp;
            uint32_t b[2] = { f2tf(PS[nr * 36 + kb + tig]), f2tf(PS[nr * 36 + kb + tig + 4]) };
            mma_tf32(acB[nt], aV, b);
        }
    }
    __syncthreads();

#pragma unroll
    for (int nt = 0; nt < 4; nt++) {
        int col = wnA + nt * 8 + tig * 2;
        *(float2*)&ACs[(wm + grp) * 68 + col]     = make_float2(acA[nt][0], acA[nt][1]);
        *(float2*)&ACs[(wm + grp + 8) * 68 + col] = make_float2(acA[nt][2], acA[nt][3]);
    }
#pragma unroll
    for (int nt = 0; nt < 8; nt++) {
        int col = wnB + nt * 8 + tig * 2;
        *(float2*)&BDs[(wm + grp) * 132 + col]     = make_float2(acB[nt][0], acB[nt][1]);
        *(float2*)&BDs[(wm + grp + 8) * 132 + col] = make_float2(acB[nt][2], acB[nt][3]);
    }
    __syncthreads();

    const float scal = 0.17677669529663687f;   // 1/sqrt(32)
    const int cc = (tid & 15) * 4;
    const int rb = tid >> 4;
#pragma unroll
    for (int it = 0; it < 4; it++) {
        int r = rb + it * 16;
        int off = 63 - r + cc;
        float4 o;
        o.x = (ACs[r * 68 + cc + 0] + BDs[r * 132 + off + 0]) * scal;
        o.y = (ACs[r * 68 + cc + 1] + BDs[r * 132 + off + 1]) * scal;
        o.z = (ACs[r * 68 + cc + 2] + BDs[r * 132 + off + 2]) * scal;
        o.w = (ACs[r * 68 + cc + 3] + BDs[r * 132 + off + 3]) * scal;
        *(float4*)(total + (((size_t)nh) << 20) + (size_t)(l0 + r) * L_ + s0 + cc) = o;
    }
}

// ---- fused proj_in + scores_out + softmax: one block per (n,l) row ------------
__global__ __launch_bounds__(256) void out_softmax_kernel(
    float* __restrict__ total, const float* __restrict__ asi,
    const float* __restrict__ projIn, const float* __restrict__ projOut,
    float* __restrict__ scores_out)
{
    __shared__ float ts[8][1028];
    __shared__ float pin[64], pout[64];
    __shared__ float red[8][8];
    const int tid = threadIdx.x;
    const int b = blockIdx.x;
    const int n = b >> 10, l = b & 1023;
    if (tid < 64) { pin[tid] = projIn[tid]; pout[tid] = projOut[tid]; }

#pragma unroll
    for (int h = 0; h < 8; h++) {
        float4 v = *(const float4*)(total + (((size_t)(n * 8 + h)) << 20)
                                          + ((size_t)l << 10) + tid * 4);
        *(float4*)&ts[h][tid * 4] = v;
    }
    __syncthreads();

    const int s = tid * 4;
    const size_t abase = ((size_t)n << 23) + ((size_t)l << 13) + ((size_t)s << 3);
    for (int js = 0; js < 4; js++) {
        float4 a0 = *(const float4*)(asi + abase + js * 8);
        float4 a1 = *(const float4*)(asi + abase + js * 8 + 4);
        float a[8] = {a0.x, a0.y, a0.z, a0.w, a1.x, a1.y, a1.z, a1.w};
        float tn8[8];
#pragma unroll
        for (int h = 0; h < 8; h++) {
            float t = ts[h][s + js];
#pragma unroll
            for (int g = 0; g < 8; g++) t = fmaf(a[g], pin[g * 8 + h], t);
            tn8[h] = t;
        }
        float o[8];
#pragma unroll
        for (int g = 0; g < 8; g++) {
            float sum = a[g];
#pragma unroll
            for (int h = 0; h < 8; h++) sum = fmaf(tn8[h], pout[h * 8 + g], sum);
            o[g] = sum;
        }
        *(float4*)(scores_out + abase + js * 8)     = make_float4(o[0], o[1], o[2], o[3]);
        *(float4*)(scores_out + abase + js * 8 + 4) = make_float4(o[4], o[5], o[6], o[7]);
#pragma unroll
        for (int h = 0; h < 8; h++) ts[h][s + js] = tn8[h];
    }

    float mh[8];
#pragma unroll
    for (int h = 0; h < 8; h++) {
        float m = fmaxf(fmaxf(ts[h][s], ts[h][s+1]), fmaxf(ts[h][s+2], ts[h][s+3]));
#pragma unroll
        for (int o = 16; o > 0; o >>= 1) m = fmaxf(m, __shfl_xor_sync(0xffffffffu, m, o));
        mh[h] = m;
    }
    if ((tid & 31) == 0)
#pragma unroll
        for (int h = 0; h < 8; h++) red[h][tid >> 5] = mh[h];
    __syncthreads();
#pragma unroll
    for (int h = 0; h < 8; h++) {
        float m = red[h][0];
#pragma unroll
        for (int w = 1; w < 8; w++) m = fmaxf(m, red[h][w]);
        mh[h] = m;
    }
    __syncthreads();

    float sh[8];
#pragma unroll
    for (int h = 0; h < 8; h++) {
        float s0 = 0.f;
#pragma unroll
        for (int js = 0; js < 4; js++) {
            float e = expf(ts[h][s + js] - mh[h]);
            ts[h][s + js] = e;
            s0 += e;
        }
#pragma unroll
        for (int o = 16; o > 0; o >>= 1) s0 += __shfl_xor_sync(0xffffffffu, s0, o);
        sh[h] = s0;
    }
    if ((tid & 31) == 0)
#pragma unroll
        for (int h = 0; h < 8; h++) red[h][tid >> 5] = sh[h];
    __syncthreads();
#pragma unroll
    for (int h = 0; h < 8; h++) {
        float ss = red[h][0] + red[h][1] + red[h][2] + red[h][3]
                 + red[h][4] + red[h][5] + red[h][6] + red[h][7];
        float inv = 1.f / ss;
        float4 o = make_float4(ts[h][s]*inv, ts[h][s+1]*inv, ts[h][s+2]*inv, ts[h][s+3]*inv);
        *(float4*)(total + (((size_t)(n * 8 + h)) << 20) + ((size_t)l << 10) + s) = o;
    }
}

// -------- ctx[l,n,h*32+d] = sum_s attn[n,h,l,s] * v[s,n,h,d] -------------------
__global__ __launch_bounds__(256) void av_kernel(
    const float* __restrict__ attn, const float* __restrict__ qkv,
    float* __restrict__ ctx)
{
    const int nh = blockIdx.y;
    const int n = nh >> 3, h = nh & 7;
    const int l0 = blockIdx.x * 64;
    __shared__ float As[64][65];
    __shared__ float Vs[64][33];
    const int tid = threadIdx.x;
    const int col = tid & 31;
    const int rg  = tid >> 5;
    float acc[8] = {};
    const float* Abase = attn + (((size_t)nh) << 20) + (((size_t)l0) << 10);
    for (int s0 = 0; s0 < 1024; s0 += 64) {
#pragma unroll
        for (int t = 0; t < 4; t++) {
            int f4 = tid + 256 * t;
            int r = f4 >> 4;
            int c4 = (f4 & 15) * 4;
            float4 v = *(const float4*)(Abase + (((size_t)r) << 10) + s0 + c4);
            As[r][c4] = v.x; As[r][c4 + 1] = v.y; As[r][c4 + 2] = v.z; As[r][c4 + 3] = v.w;
        }
#pragma unroll
        for (int t = 0; t < 8; t++) {
            int flat = tid + 256 * t;
            int r = flat >> 5, dd = flat & 31;
            Vs[r][dd] = qkv[(size_t)((s0 + r) * NB + n) * 768 + 512 + h * 32 + dd];
        }
        __syncthreads();
#pragma unroll
        for (int kk = 0; kk < 64; kk++) {
            float vv = Vs[kk][col];
#pragma unroll
            for (int i = 0; i < 8; i++)
                acc[i] = fmaf(As[rg * 8 + i][kk], vv, acc[i]);
        }
        __syncthreads();
    }
#pragma unroll
    for (int i = 0; i < 8; i++) {
        int l = l0 + rg * 8 + i;
        ctx[(size_t)(l * NB + n) * 256 + h * 32 + col] = acc[i];
    }
}

// -------- GLU with 32x32 smem transpose: y(l,n,:) -> hglu(n,c,l) ---------------
__global__ __launch_bounds__(256) void glu_t_kernel(
    const float* __restrict__ y, float* __restrict__ hglu)
{
    __shared__ float sm[32][33];
    const int l0 = blockIdx.x * 32, c0 = blockIdx.y * 32, n = blockIdx.z;
    const int li = threadIdx.x >> 3;
    const int c4 = (threadIdx.x & 7) * 4;
    size_t t = (size_t)(l0 + li) * NB + n;
    float4 a = *(const float4*)(y + t * 1024 + c0 + c4);
    float4 b = *(const float4*)(y + t * 1024 + c0 + c4 + 512);
    sm[c4 + 0][li] = a.x / (1.f + expf(-b.x));
    sm[c4 + 1][li] = a.y / (1.f + expf(-b.y));
    sm[c4 + 2][li] = a.z / (1.f + expf(-b.z));
    sm[c4 + 3][li] = a.w / (1.f + expf(-b.w));
    __syncthreads();
    const int c = threadIdx.x >> 3;
    const int l4 = (threadIdx.x & 7) * 4;
    float4 o = make_float4(sm[c][l4], sm[c][l4 + 1], sm[c][l4 + 2], sm[c][l4 + 3]);
    *(float4*)(hglu + (((size_t)(n * 512 + c0 + c)) << 10) + l0 + l4) = o;
}

// -------- depthwise conv(K=31) + bias + DoubleSwish, coalesced writes ---------
__global__ __launch_bounds__(256) void dwconv_kernel(
    const float* __restrict__ hglu, const float* __restrict__ w,
    const float* __restrict__ b, float* __restrict__ out)
{
    __shared__ float in_s[32 * 161];
    __shared__ float w_s[32 * 33];
    const int l0 = blockIdx.x * 128;
    const int c0 = blockIdx.y * 32;
    const int n  = blockIdx.z;

    for (int idx = threadIdx.x; idx < 32 * 160; idx += 256) {
        int row = idx / 160, col = idx % 160;
        int gl = l0 + col - 15;
        float v = 0.f;
        if (col < 158 && gl >= 0 && gl < L_)
            v = hglu[(((size_t)(n * 512 + c0 + row)) << 10) + gl];
        in_s[row * 161 + col] = v;
    }
    for (int idx = threadIdx.x; idx < 32 * KW; idx += 256) {
        int c = idx / KW, k = idx % KW;
        w_s[c * 33 + k] = w[(c0 + c) * KW + k];
    }
    __syncthreads();

    const int ci = threadIdx.x & 31;
    const int lq = threadIdx.x >> 5;
    const float bb = b[c0 + ci];
#pragma unroll
    for (int lt = 0; lt < 16; lt++) {
        int ll = lt * 8 + lq;
        float s = bb;
#pragma unroll
        for (int k = 0; k < KW; k++)
            s = fmaf(in_s[ci * 161 + ll + k], w_s[ci * 33 + k], s);
        float v = s / (1.f + expf(1.f - s));
        out[(((size_t)((l0 + ll) * NB + n)) << 9) + c0 + ci] = v;
    }
}

// -------- BasicNorm -> d_out ---------------------------------------------------
__global__ __launch_bounds__(128) void norm_kernel(
    const float* __restrict__ x, const float* __restrict__ leps,
    float* __restrict__ out)
{
    __shared__ float red[4];
    const size_t base = (size_t)blockIdx.x * 512;
    float4 v = ((const float4*)(x + base))[threadIdx.x];
    float ss = v.x * v.x + v.y * v.y + v.z * v.z + v.w * v.w;
#pragma unroll
    for (int o = 16; o > 0; o >>= 1) ss += __shfl_xor_sync(0xffffffffu, ss, o);
    if ((threadIdx.x & 31) == 0) red[threadIdx.x >> 5] = ss;
    __syncthreads();
    float tot = red[0] + red[1] + red[2] + red[3];
    float scale = rsqrtf(tot * (1.f / 512.f) + expf(leps[0]));
    ((float4*)(out + base))[threadIdx.x] =
        make_float4(v.x * scale, v.y * scale, v.z * scale, v.w * scale);
}

// ------------------------------- launcher -------------------------------------
extern "C" void kernel_launch(void* const* d_in, const int* in_sizes, int n_in,
                              void* d_out, int out_size)
{
    const float* src      = (const float*)d_in[0];
    const float* pos_emb  = (const float*)d_in[1];
    const float* asi      = (const float*)d_in[2];
    const float* w_in     = (const float*)d_in[3];
    const float* b_in     = (const float*)d_in[4];
    const float* w_pos    = (const float*)d_in[5];
    const float* pbu      = (const float*)d_in[6];
    const float* pbv      = (const float*)d_in[7];
    const float* projIn   = (const float*)d_in[8];
    const float* projOut  = (const float*)d_in[9];
    const float* w_out    = (const float*)d_in[10];
    const float* b_out    = (const float*)d_in[11];
    const float* w_ff1m   = (const float*)d_in[12];
    const float* b_ff1m   = (const float*)d_in[13];
    const float* w_ff2m   = (const float*)d_in[14];
    const float* b_ff2m   = (const float*)d_in[15];
    const float* w_ff1    = (const float*)d_in[16];
    const float* b_ff1    = (const float*)d_in[17];
    const float* w_ff2    = (const float*)d_in[18];
    const float* b_ff2    = (const float*)d_in[19];
    const float* w_pw1    = (const float*)d_in[20];
    const float* b_pw1    = (const float*)d_in[21];
    const float* w_dw     = (const float*)d_in[22];
    const float* b_dw     = (const float*)d_in[23];
    const float* w_pw2    = (const float*)d_in[24];
    const float* b_pw2    = (const float*)d_in[25];
    const float* leps     = (const float*)d_in[26];

    float* out        = (float*)d_out;
    float* out_scores = out + (size_t)TOK * E_;

    float *h1, *x, *qkv, *p, *total, *ctx, *x2, *y, *hglu, *hct, *x3, *x4, *wtf;
    cudaGetSymbolAddress((void**)&h1,   g_h1);
    cudaGetSymbolAddress((void**)&x,    g_x);
    cudaGetSymbolAddress((void**)&qkv,  g_qkv);
    cudaGetSymbolAddress((void**)&p,    g_p);
    cudaGetSymbolAddress((void**)&total,g_total);
    cudaGetSymbolAddress((void**)&ctx,  g_ctx);
    cudaGetSymbolAddress((void**)&x2,   g_x2);
    cudaGetSymbolAddress((void**)&y,    g_y);
    cudaGetSymbolAddress((void**)&hglu, g_hglu);
    cudaGetSymbolAddress((void**)&hct,  g_hct);
    cudaGetSymbolAddress((void**)&x3,   g_x3);
    cudaGetSymbolAddress((void**)&x4,   g_x4);
    cudaGetSymbolAddress((void**)&wtf,  g_wtf);

    static bool attr_set = false;
    if (!attr_set) {
        cudaFuncSetAttribute(tgemm<0>, cudaFuncAttributeMaxDynamicSharedMemorySize, TG_SMEM);
        cudaFuncSetAttribute(tgemm<1>, cudaFuncAttributeMaxDynamicSharedMemorySize, TG_SMEM);
        cudaFuncSetAttribute(tgemm<2>, cudaFuncAttributeMaxDynamicSharedMemorySize, TG_SMEM);
        cudaFuncSetAttribute(scores_mma_kernel, cudaFuncAttributeMaxDynamicSharedMemorySize, SC_SMEM);
        attr_set = true;
    }

    // prepass: tf32-round all B (weight) operands
    CvtArgs ca;
    ca.src[0] = w_ff1m; ca.dstoff[0] = OFF_FF1M; ca.n4[0] = (DFF_ * E_) / 4;
    ca.src[1] = w_ff2m; ca.dstoff[1] = OFF_FF2M; ca.n4[1] = (E_ * DFF_) / 4;
    ca.src[2] = w_in;   ca.dstoff[2] = OFF_IN;   ca.n4[2] = (768 * E_) / 4;
    ca.src[3] = w_pos;  ca.dstoff[3] = OFF_POS;  ca.n4[3] = (E2_ * E_) / 4;
    ca.src[4] = w_out;  ca.dstoff[4] = OFF_OUT;  ca.n4[4] = (E_ * E2_) / 4;
    ca.src[5] = w_pw1;  ca.dstoff[5] = OFF_PW1;  ca.n4[5] = (1024 * E_) / 4;
    ca.src[6] = w_pw2;  ca.dstoff[6] = OFF_PW2;  ca.n4[6] = (E_ * E_) / 4;
    ca.src[7] = w_ff1;  ca.dstoff[7] = OFF_FF1;  ca.n4[7] = (DFF_ * E_) / 4;
    ca.src[8] = w_ff2;  ca.dstoff[8] = OFF_FF2;  ca.n4[8] = (E_ * DFF_) / 4;
    cvtw_kernel<<<dim3(1024, 9), 256>>>(ca);

    // macaron FFN
    tgemm<1><<<dim3(DFF_ / 128, TOK / 128), 128, TG_SMEM>>>(src, wtf + OFF_FF1M, b_ff1m, nullptr, h1, TOK, DFF_, E_);
    tgemm<2><<<dim3(E_ / 128, TOK / 128), 128, TG_SMEM>>>(h1, wtf + OFF_FF2M, b_ff2m, src, x, TOK, E_, DFF_);

    // attention inputs
    tgemm<0><<<dim3(768 / 128, TOK / 128), 128, TG_SMEM>>>(x, wtf + OFF_IN, b_in, nullptr, qkv, TOK, 768, E_);
    tgemm<0><<<dim3(2, 16), 128, TG_SMEM>>>(pos_emb, wtf + OFF_POS, nullptr, nullptr, p, PM, 256, E_);

    // raw scores (tf32 MMA) -> fused proj_in + scores_out + softmax -> AV
    scores_mma_kernel<<<dim3(16, 16, 32), 256, SC_SMEM>>>(qkv, p, pbu, pbv, total);
    out_softmax_kernel<<<4096, 256>>>(total, asi, projIn, projOut, out_scores);
    av_kernel<<<dim3(16, 32), 256>>>(total, qkv, ctx);
    tgemm<2><<<dim3(E_ / 128, TOK / 128), 128, TG_SMEM>>>(ctx, wtf + OFF_OUT, b_out, x, x2, TOK, E_, E2_);

    // conv module
    tgemm<0><<<dim3(1024 / 128, TOK / 128), 128, TG_SMEM>>>(x2, wtf + OFF_PW1, b_pw1, nullptr, y, TOK, 1024, E_);
    glu_t_kernel<<<dim3(32, 16, NB), 256>>>(y, hglu);
    dwconv_kernel<<<dim3(8, 16, NB), 256>>>(hglu, w_dw, b_dw, hct);
    tgemm<2><<<dim3(E_ / 128, TOK / 128), 128, TG_SMEM>>>(hct, wtf + OFF_PW2, b_pw2, x2, x3, TOK, E_, E_);

    // final FFN + BasicNorm
    tgemm<1><<<dim3(DFF_ / 128, TOK / 128), 128, TG_SMEM>>>(x3, wtf + OFF_FF1, b_ff1, nullptr, h1, TOK, DFF_, E_);
    tgemm<2><<<dim3(E_ / 128, TOK / 128), 128, TG_SMEM>>>(h1, wtf + OFF_FF2, b_ff2, x3, x4, TOK, E_, DFF_);
    norm_kernel<<<TOK, 128>>>(x4, leps, out);
}